// round 1
// baseline (speedup 1.0000x reference)
#include <cuda_runtime.h>
#include <cstdint>
#include <math.h>

#define NA 4096
#define NB 4096
#define D  256
#define H  4
#define DK 64
#define STRIDE 68   // 64 + 4 pad, keeps 16B alignment (68*4 = 272 bytes)

// ---------------- scratch (no cudaMalloc allowed) ----------------
__device__ float g_Q[NA * D];           // Q projection, pre-scaled by 1/8
__device__ float g_K[NB * D];
__device__ float g_V[NB * D];
__device__ float g_ctx[H * NA * DK];    // per-head context
__device__ int   g_mask_is_i32;

typedef unsigned long long u64;

// ---------------- packed f32x2 helpers (sm_103a) ----------------
__device__ __forceinline__ u64 pack2(float x, float y) {
    u64 r; asm("mov.b64 %0, {%1,%2};" : "=l"(r) : "f"(x), "f"(y)); return r;
}
__device__ __forceinline__ void unpack2(u64 v, float& x, float& y) {
    asm("mov.b64 {%0,%1}, %2;" : "=f"(x), "=f"(y) : "l"(v));
}
__device__ __forceinline__ u64 fma2(u64 a, u64 b, u64 c) {
    u64 d; asm("fma.rn.f32x2 %0, %1, %2, %3;" : "=l"(d) : "l"(a), "l"(b), "l"(c)); return d;
}
__device__ __forceinline__ u64 mul2(u64 a, u64 b) {
    u64 d; asm("mul.rn.f32x2 %0, %1, %2;" : "=l"(d) : "l"(a), "l"(b)); return d;
}
__device__ __forceinline__ float sani(float x) {
    if (isnan(x)) return 0.0f;
    if (isinf(x)) return x > 0.0f ? 1.0f : -1.0f;
    return x;
}

// ---------------- mask dtype detector ----------------
// int32 bool array -> every 4-byte word is 0 or 1.
// uint8 bool array -> words are 4 packed random 0/1 bytes; almost surely >1 somewhere.
__global__ void detect_mask_kernel(const unsigned* __restrict__ m) {
    __shared__ int bad;
    if (threadIdx.x == 0) bad = 0;
    __syncthreads();
    for (int i = threadIdx.x; i < 4096; i += blockDim.x) {
        if (m[i] > 1u) bad = 1;
    }
    __syncthreads();
    if (threadIdx.x == 0) g_mask_is_i32 = bad ? 0 : 1;
}

// ---------------- projections: C = sanitize(X) @ W^T ----------------
// grid (64, 4, 3), block 256. z: 0 = Q (scaled 1/8), 1 = K, 2 = V.
__global__ __launch_bounds__(256) void proj_kernel(
    const float* __restrict__ a_z, const float* __restrict__ bv_z,
    const float* __restrict__ Wq, const float* __restrict__ Wk,
    const float* __restrict__ Wv)
{
    __shared__ float Xs[32][STRIDE];
    __shared__ float Ws[32][STRIDE];

    const int z = blockIdx.z;
    const float* X = (z == 0) ? a_z : bv_z;
    const float* W = (z == 0) ? Wq : (z == 1) ? Wk : Wv;
    float* C       = (z == 0) ? g_Q : (z == 1) ? g_K : g_V;
    const float outscale = (z == 0) ? 0.125f : 1.0f;

    const int tid = threadIdx.x;
    const int tx = tid & 15, ty = tid >> 4;
    const int r0 = blockIdx.x * 64, c0 = blockIdx.y * 64;

    u64 acc[2][4];
#pragma unroll
    for (int p = 0; p < 2; p++)
#pragma unroll
        for (int j = 0; j < 4; j++) acc[p][j] = 0ull;

    for (int k0 = 0; k0 < D; k0 += 32) {
        __syncthreads();
#pragma unroll
        for (int s = 0; s < 2; s++) {
            int idx = tid * 2 + s;       // 0..511
            int row = idx >> 3;          // 0..63
            int k4  = (idx & 7) * 4;     // 0..28
            float4 v = *(const float4*)&X[(size_t)(r0 + row) * D + k0 + k4];
            Xs[k4 + 0][row] = sani(v.x);
            Xs[k4 + 1][row] = sani(v.y);
            Xs[k4 + 2][row] = sani(v.z);
            Xs[k4 + 3][row] = sani(v.w);
            float4 w = *(const float4*)&W[(size_t)(c0 + row) * D + k0 + k4];
            Ws[k4 + 0][row] = w.x;
            Ws[k4 + 1][row] = w.y;
            Ws[k4 + 2][row] = w.z;
            Ws[k4 + 3][row] = w.w;
        }
        __syncthreads();
#pragma unroll 8
        for (int kk = 0; kk < 32; kk++) {
            const u64* ap = (const u64*)&Xs[kk][ty * 4];
            u64 a0 = ap[0], a1 = ap[1];
            float4 b = *(const float4*)&Ws[kk][tx * 4];
            u64 b0 = pack2(b.x, b.x), b1 = pack2(b.y, b.y);
            u64 b2 = pack2(b.z, b.z), b3 = pack2(b.w, b.w);
            acc[0][0] = fma2(a0, b0, acc[0][0]);
            acc[0][1] = fma2(a0, b1, acc[0][1]);
            acc[0][2] = fma2(a0, b2, acc[0][2]);
            acc[0][3] = fma2(a0, b3, acc[0][3]);
            acc[1][0] = fma2(a1, b0, acc[1][0]);
            acc[1][1] = fma2(a1, b1, acc[1][1]);
            acc[1][2] = fma2(a1, b2, acc[1][2]);
            acc[1][3] = fma2(a1, b3, acc[1][3]);
        }
    }
#pragma unroll
    for (int p = 0; p < 2; p++)
#pragma unroll
        for (int j = 0; j < 4; j++) {
            float x, y; unpack2(acc[p][j], x, y);
            int r = ty * 4 + p * 2;
            int c = c0 + tx * 4 + j;
            C[(size_t)(r0 + r) * D + c]     = x * outscale;
            C[(size_t)(r0 + r + 1) * D + c] = y * outscale;
        }
}

// ---------------- fused flash attention ----------------
// grid (64 q-tiles, 4 heads), block 256 (16x16 thread grid, 4x4 micro-tile).
// Smem: Qs[64][68] (k-major), KP[64][68] (K k-major, reused as P b-major), Vs[64][64].
__global__ __launch_bounds__(256, 2) void attn_kernel(
    const unsigned char* __restrict__ mask_u8,
    const int* __restrict__ mask_i32,
    const float* __restrict__ weight)
{
    extern __shared__ float sm[];
    float* Qs = sm;
    float* KP = sm + 64 * STRIDE;
    float* Vs = sm + 2 * 64 * STRIDE;

    const int tid = threadIdx.x;
    const int tx = tid & 15, ty = tid >> 4;
    const int head = blockIdx.y;
    const int q0 = blockIdx.x * 64;
    const int mi32 = g_mask_is_i32;

    // Q tile -> smem transposed [k][row]
#pragma unroll
    for (int s = 0; s < 4; s++) {
        int idx = tid + s * 256;       // 0..1023
        int r  = idx >> 4;             // 0..63
        int k4 = (idx & 15) * 4;       // 0..60
        float4 v = *(const float4*)&g_Q[(size_t)(q0 + r) * D + head * DK + k4];
        Qs[(k4 + 0) * STRIDE + r] = v.x;
        Qs[(k4 + 1) * STRIDE + r] = v.y;
        Qs[(k4 + 2) * STRIDE + r] = v.z;
        Qs[(k4 + 3) * STRIDE + r] = v.w;
    }

    u64 o2[2][4];
#pragma unroll
    for (int p = 0; p < 2; p++)
#pragma unroll
        for (int j = 0; j < 4; j++) o2[p][j] = 0ull;
    float mrow[4] = {-INFINITY, -INFINITY, -INFINITY, -INFINITY};
    float lrow[4] = {0.f, 0.f, 0.f, 0.f};

    for (int b0 = 0; b0 < NB; b0 += 64) {
        __syncthreads();   // previous iter done with KP / Vs
        // K (transposed) and V (natural) tiles
#pragma unroll
        for (int s = 0; s < 4; s++) {
            int idx = tid + s * 256;
            int r  = idx >> 4;
            int k4 = (idx & 15) * 4;
            float4 kv = *(const float4*)&g_K[(size_t)(b0 + r) * D + head * DK + k4];
            KP[(k4 + 0) * STRIDE + r] = kv.x;
            KP[(k4 + 1) * STRIDE + r] = kv.y;
            KP[(k4 + 2) * STRIDE + r] = kv.z;
            KP[(k4 + 3) * STRIDE + r] = kv.w;
            float4 vv = *(const float4*)&g_V[(size_t)(b0 + r) * D + head * DK + k4];
            *(float4*)&Vs[r * 64 + k4] = vv;
        }
        // weight + mask micro-tile into registers (coalesced float4 / 16B)
        float wreg[4][4];
        unsigned mreg[4];
#pragma unroll
        for (int i = 0; i < 4; i++) {
            size_t off = (size_t)(q0 + ty * 4 + i) * NB + b0 + tx * 4;
            float4 w = *(const float4*)&weight[off];
            wreg[i][0] = sani(w.x); wreg[i][1] = sani(w.y);
            wreg[i][2] = sani(w.z); wreg[i][3] = sani(w.w);
            unsigned mb;
            if (mi32) {
                int4 m4 = *(const int4*)&mask_i32[off];
                mb = (unsigned)(m4.x != 0) | ((unsigned)(m4.y != 0) << 1)
                   | ((unsigned)(m4.z != 0) << 2) | ((unsigned)(m4.w != 0) << 3);
            } else {
                uchar4 m4 = *(const uchar4*)&mask_u8[off];
                mb = (unsigned)(m4.x != 0) | ((unsigned)(m4.y != 0) << 1)
                   | ((unsigned)(m4.z != 0) << 2) | ((unsigned)(m4.w != 0) << 3);
            }
            mreg[i] = mb;
        }
        __syncthreads();

        // S = (Q/8) K^T  (row-paired f32x2 accumulators)
        u64 s2[2][4];
#pragma unroll
        for (int p = 0; p < 2; p++)
#pragma unroll
            for (int j = 0; j < 4; j++) s2[p][j] = 0ull;
#pragma unroll 8
        for (int kk = 0; kk < 64; kk++) {
            const u64* ap = (const u64*)&Qs[kk * STRIDE + ty * 4];
            u64 a0 = ap[0], a1 = ap[1];
            float4 b = *(const float4*)&KP[kk * STRIDE + tx * 4];
            u64 b0 = pack2(b.x, b.x), b1 = pack2(b.y, b.y);
            u64 b2 = pack2(b.z, b.z), b3 = pack2(b.w, b.w);
            s2[0][0] = fma2(a0, b0, s2[0][0]);
            s2[0][1] = fma2(a0, b1, s2[0][1]);
            s2[0][2] = fma2(a0, b2, s2[0][2]);
            s2[0][3] = fma2(a0, b3, s2[0][3]);
            s2[1][0] = fma2(a1, b0, s2[1][0]);
            s2[1][1] = fma2(a1, b1, s2[1][1]);
            s2[1][2] = fma2(a1, b2, s2[1][2]);
            s2[1][3] = fma2(a1, b3, s2[1][3]);
        }
        float s[4][4];
#pragma unroll
        for (int j = 0; j < 4; j++) {
            unpack2(s2[0][j], s[0][j], s[1][j]);
            unpack2(s2[1][j], s[2][j], s[3][j]);
        }

        // mask -> +weight -> clip -> online softmax per row
        float alpha[4];
#pragma unroll
        for (int i = 0; i < 4; i++) {
#pragma unroll
            for (int j = 0; j < 4; j++) {
                float v = ((mreg[i] >> j) & 1u) ? s[i][j] : -10000.0f;
                v += wreg[i][j];
                v = fminf(10.0f, fmaxf(-10.0f, v));
                s[i][j] = v;
            }
            float rm = fmaxf(fmaxf(s[i][0], s[i][1]), fmaxf(s[i][2], s[i][3]));
            rm = fmaxf(rm, __shfl_xor_sync(0xffffffffu, rm, 1, 16));
            rm = fmaxf(rm, __shfl_xor_sync(0xffffffffu, rm, 2, 16));
            rm = fmaxf(rm, __shfl_xor_sync(0xffffffffu, rm, 4, 16));
            rm = fmaxf(rm, __shfl_xor_sync(0xffffffffu, rm, 8, 16));
            float mnew = fmaxf(mrow[i], rm);
            alpha[i] = expf(mrow[i] - mnew);   // first iter: exp(-inf) = 0
            mrow[i] = mnew;
            float rs = 0.0f;
#pragma unroll
            for (int j = 0; j < 4; j++) {
                float e = expf(s[i][j] - mnew);
                s[i][j] = e;
                rs += e;
            }
            rs += __shfl_xor_sync(0xffffffffu, rs, 1, 16);
            rs += __shfl_xor_sync(0xffffffffu, rs, 2, 16);
            rs += __shfl_xor_sync(0xffffffffu, rs, 4, 16);
            rs += __shfl_xor_sync(0xffffffffu, rs, 8, 16);
            lrow[i] = lrow[i] * alpha[i] + rs;
        }
        // rescale accumulator
        {
            u64 al0 = pack2(alpha[0], alpha[1]);
            u64 al1 = pack2(alpha[2], alpha[3]);
#pragma unroll
            for (int j = 0; j < 4; j++) {
                o2[0][j] = mul2(o2[0][j], al0);
                o2[1][j] = mul2(o2[1][j], al1);
            }
        }
        __syncthreads();   // all threads done reading K from KP
        // write P into KP as [b][row]
#pragma unroll
        for (int j = 0; j < 4; j++) {
            float4 pv = make_float4(s[0][j], s[1][j], s[2][j], s[3][j]);
            *(float4*)&KP[(tx * 4 + j) * STRIDE + ty * 4] = pv;
        }
        __syncthreads();
        // O += P @ V
#pragma unroll 8
        for (int bb = 0; bb < 64; bb++) {
            const u64* pp = (const u64*)&KP[bb * STRIDE + ty * 4];
            u64 p0 = pp[0], p1 = pp[1];
            float4 v = *(const float4*)&Vs[bb * 64 + tx * 4];
            u64 v0 = pack2(v.x, v.x), v1 = pack2(v.y, v.y);
            u64 v2 = pack2(v.z, v.z), v3 = pack2(v.w, v.w);
            o2[0][0] = fma2(p0, v0, o2[0][0]);
            o2[0][1] = fma2(p0, v1, o2[0][1]);
            o2[0][2] = fma2(p0, v2, o2[0][2]);
            o2[0][3] = fma2(p0, v3, o2[0][3]);
            o2[1][0] = fma2(p1, v0, o2[1][0]);
            o2[1][1] = fma2(p1, v1, o2[1][1]);
            o2[1][2] = fma2(p1, v2, o2[1][2]);
            o2[1][3] = fma2(p1, v3, o2[1][3]);
        }
    }

    // epilogue: context = O / l, into per-head scratch
    const float inv0 = 1.0f / lrow[0], inv1 = 1.0f / lrow[1];
    const float inv2 = 1.0f / lrow[2], inv3 = 1.0f / lrow[3];
    float* ctx = &g_ctx[(size_t)head * NA * DK];
#pragma unroll
    for (int j = 0; j < 4; j++) {
        float x0, y0, x1, y1;
        unpack2(o2[0][j], x0, y0);
        unpack2(o2[1][j], x1, y1);
        int c = tx * 4 + j;
        ctx[(size_t)(q0 + ty * 4 + 0) * DK + c] = x0 * inv0;
        ctx[(size_t)(q0 + ty * 4 + 1) * DK + c] = y0 * inv1;
        ctx[(size_t)(q0 + ty * 4 + 2) * DK + c] = x1 * inv2;
        ctx[(size_t)(q0 + ty * 4 + 3) * DK + c] = y1 * inv3;
    }
}

// ---------------- finalize: head mean + influence(=1) ----------------
__global__ void finalize_kernel(float* __restrict__ out)
{
    int idx = blockIdx.x * blockDim.x + threadIdx.x;
    if (idx < NA * DK) {
        out[idx] = 0.25f * (g_ctx[idx] + g_ctx[NA * DK + idx]
                          + g_ctx[2 * NA * DK + idx] + g_ctx[3 * NA * DK + idx]);
    }
    if (idx < NA) {
        // influence = sum_b mean_h softmax(...) == 1 exactly
        out[NA * DK + idx] = 1.0f;
    }
}

// ---------------- launch ----------------
extern "C" void kernel_launch(void* const* d_in, const int* in_sizes, int n_in,
                              void* d_out, int out_size)
{
    const float* a_z   = (const float*)d_in[0];
    const float* bv_z  = (const float*)d_in[1];
    const void*  maskp = d_in[2];
    const float* weight= (const float*)d_in[3];
    const float* Wq    = (const float*)d_in[4];
    const float* Wk    = (const float*)d_in[5];
    const float* Wv    = (const float*)d_in[6];
    float* out = (float*)d_out;

    const int smem_bytes = (2 * 64 * STRIDE + 64 * 64) * (int)sizeof(float); // 51200
    cudaFuncSetAttribute(attn_kernel, cudaFuncAttributeMaxDynamicSharedMemorySize, smem_bytes);

    detect_mask_kernel<<<1, 256>>>((const unsigned*)maskp);
    proj_kernel<<<dim3(NA / 64, D / 64, 3), 256>>>(a_z, bv_z, Wq, Wk, Wv);
    attn_kernel<<<dim3(NA / 64, H), 256, smem_bytes>>>(
        (const unsigned char*)maskp, (const int*)maskp, weight);
    finalize_kernel<<<(NA * DK + 255) / 256, 256>>>(out);
}

// round 3
// speedup vs baseline: 1.6094x; 1.6094x over previous
#include <cuda_runtime.h>
#include <cuda_bf16.h>
#include <cstdint>
#include <math.h>

#define NA 4096
#define NB 4096
#define D  256
#define H  4
#define DK 64
#define BM 128
#define BN 64
#define NITER (NB / BN)   // 64

// ---------------- global scratch (no cudaMalloc allowed) ----------------
__device__ __nv_bfloat16 g_Qhi[H * NA * DK], g_Qlo[H * NA * DK];
__device__ __nv_bfloat16 g_Khi[H * NB * DK], g_Klo[H * NB * DK];
__device__ __nv_bfloat16 g_Vthi[H * DK * NB], g_Vtlo[H * DK * NB];
__device__ float g_ctx[H * NA * DK];
__device__ int   g_mask_is_i32;

typedef unsigned long long u64;
typedef unsigned int u32;

// smem layout (bytes): Qhi 16K @0, Qlo 16K @16384, KV buf{0,1} 32K each @32768
//   KV buf: +0 Khi(8K)  +8192 Klo  +16384 Vthi  +24576 Vtlo
#define SMQ    0
#define SMKV(b) (32768 + (b) * 32768)
#define SM_TOTAL 98304

// ---------------- helpers ----------------
__device__ __forceinline__ u64 pack2(float x, float y) {
    u64 r; asm("mov.b64 %0, {%1,%2};" : "=l"(r) : "f"(x), "f"(y)); return r;
}
__device__ __forceinline__ void unpack2(u64 v, float& x, float& y) {
    asm("mov.b64 {%0,%1}, %2;" : "=f"(x), "=f"(y) : "l"(v));
}
__device__ __forceinline__ u64 fma2(u64 a, u64 b, u64 c) {
    u64 d; asm("fma.rn.f32x2 %0, %1, %2, %3;" : "=l"(d) : "l"(a), "l"(b), "l"(c)); return d;
}
__device__ __forceinline__ float sani(float x) {
    if (isnan(x)) return 0.0f;
    if (isinf(x)) return x > 0.0f ? 1.0f : -1.0f;
    return x;
}
__device__ __forceinline__ float ex2f(float x) {
    float y; asm("ex2.approx.ftz.f32 %0, %1;" : "=f"(y) : "f"(x)); return y;
}
__device__ __forceinline__ u32 smem_u32(const void* p) {
    u32 a; asm("{ .reg .u64 t; cvta.to.shared.u64 t, %1; cvt.u32.u64 %0, t; }" : "=r"(a) : "l"(p));
    return a;
}
__device__ __forceinline__ void cp16(u32 dst, const void* src) {
    asm volatile("cp.async.cg.shared.global [%0], [%1], 16;" :: "r"(dst), "l"(src));
}
__device__ __forceinline__ void cp_commit() { asm volatile("cp.async.commit_group;"); }
__device__ __forceinline__ void cp_wait0()  { asm volatile("cp.async.wait_group 0;"); }

__device__ __forceinline__ void ldsm4(u32 addr, u32& r0, u32& r1, u32& r2, u32& r3) {
    asm volatile("ldmatrix.sync.aligned.m8n8.x4.shared.b16 {%0,%1,%2,%3}, [%4];"
                 : "=r"(r0), "=r"(r1), "=r"(r2), "=r"(r3) : "r"(addr));
}
__device__ __forceinline__ void mma16816(float* c, u32 a0, u32 a1, u32 a2, u32 a3, u32 b0, u32 b1) {
    asm volatile(
        "mma.sync.aligned.m16n8k16.row.col.f32.bf16.bf16.f32 "
        "{%0,%1,%2,%3}, {%4,%5,%6,%7}, {%8,%9}, {%0,%1,%2,%3};"
        : "+f"(c[0]), "+f"(c[1]), "+f"(c[2]), "+f"(c[3])
        : "r"(a0), "r"(a1), "r"(a2), "r"(a3), "r"(b0), "r"(b1));
}
// pack two floats to bf16x2, 'lo' in low 16 bits
__device__ __forceinline__ u32 packbf(float lo, float hi) {
    u32 d; asm("cvt.rn.bf16x2.f32 %0, %1, %2;" : "=r"(d) : "f"(hi), "f"(lo)); return d;
}
__device__ __forceinline__ float bf_lo(u32 v) { return __uint_as_float(v << 16); }
__device__ __forceinline__ float bf_hi(u32 v) { return __uint_as_float(v & 0xffff0000u); }
// swizzled smem address: tile rows are 128B, chunk(16B) XOR row
__device__ __forceinline__ u32 swaddr(u32 base, int row, int colhalf) {
    int ch = colhalf >> 3;
    return base + row * 128 + (((ch ^ (row & 7)) << 4));
}

// ---------------- mask dtype detector ----------------
__global__ void detect_mask_kernel(const unsigned* __restrict__ m) {
    __shared__ int bad;
    if (threadIdx.x == 0) bad = 0;
    __syncthreads();
    for (int i = threadIdx.x; i < 4096; i += blockDim.x)
        if (m[i] > 1u) bad = 1;
    __syncthreads();
    if (threadIdx.x == 0) g_mask_is_i32 = bad ? 0 : 1;
}

// ---------------- projections: sanitize(X) @ W^T, split to bf16 hi/lo ----------------
#define PSTRIDE 68
__global__ __launch_bounds__(256) void proj_kernel(
    const float* __restrict__ a_z, const float* __restrict__ bv_z,
    const float* __restrict__ Wq, const float* __restrict__ Wk,
    const float* __restrict__ Wv)
{
    __shared__ float Xs[32][PSTRIDE];
    __shared__ float Ws[32][PSTRIDE];

    const int z = blockIdx.z;
    const float* X = (z == 0) ? a_z : bv_z;
    const float* W = (z == 0) ? Wq : (z == 1) ? Wk : Wv;
    const float outscale = (z == 0) ? 0.125f : 1.0f;

    const int tid = threadIdx.x;
    const int tx = tid & 15, ty = tid >> 4;
    const int r0 = blockIdx.x * 64, c0 = blockIdx.y * 64;

    u64 acc[2][4];
#pragma unroll
    for (int p = 0; p < 2; p++)
#pragma unroll
        for (int j = 0; j < 4; j++) acc[p][j] = 0ull;

    for (int k0 = 0; k0 < D; k0 += 32) {
        __syncthreads();
#pragma unroll
        for (int s = 0; s < 2; s++) {
            int idx = tid * 2 + s;
            int row = idx >> 3;
            int k4  = (idx & 7) * 4;
            float4 v = *(const float4*)&X[(size_t)(r0 + row) * D + k0 + k4];
            Xs[k4 + 0][row] = sani(v.x);
            Xs[k4 + 1][row] = sani(v.y);
            Xs[k4 + 2][row] = sani(v.z);
            Xs[k4 + 3][row] = sani(v.w);
            float4 w = *(const float4*)&W[(size_t)(c0 + row) * D + k0 + k4];
            Ws[k4 + 0][row] = w.x;
            Ws[k4 + 1][row] = w.y;
            Ws[k4 + 2][row] = w.z;
            Ws[k4 + 3][row] = w.w;
        }
        __syncthreads();
#pragma unroll 8
        for (int kk = 0; kk < 32; kk++) {
            const u64* ap = (const u64*)&Xs[kk][ty * 4];
            u64 a0 = ap[0], a1 = ap[1];
            float4 b = *(const float4*)&Ws[kk][tx * 4];
            u64 b0 = pack2(b.x, b.x), b1 = pack2(b.y, b.y);
            u64 b2 = pack2(b.z, b.z), b3 = pack2(b.w, b.w);
            acc[0][0] = fma2(a0, b0, acc[0][0]);
            acc[0][1] = fma2(a0, b1, acc[0][1]);
            acc[0][2] = fma2(a0, b2, acc[0][2]);
            acc[0][3] = fma2(a0, b3, acc[0][3]);
            acc[1][0] = fma2(a1, b0, acc[1][0]);
            acc[1][1] = fma2(a1, b1, acc[1][1]);
            acc[1][2] = fma2(a1, b2, acc[1][2]);
            acc[1][3] = fma2(a1, b3, acc[1][3]);
        }
    }
#pragma unroll
    for (int p = 0; p < 2; p++)
#pragma unroll
        for (int j = 0; j < 4; j++) {
            float x, y; unpack2(acc[p][j], x, y);
            x *= outscale; y *= outscale;
            const int rr = r0 + ty * 4 + p * 2;
            const int c  = c0 + tx * 4 + j;
            const int hd = c >> 6, hc = c & 63;
            __nv_bfloat16 xh = __float2bfloat16(x);
            __nv_bfloat16 xl = __float2bfloat16(x - __bfloat162float(xh));
            __nv_bfloat16 yh = __float2bfloat16(y);
            __nv_bfloat16 yl = __float2bfloat16(y - __bfloat162float(yh));
            if (z == 0) {
                size_t o = ((size_t)hd * NA + rr) * DK + hc;
                g_Qhi[o] = xh; g_Qlo[o] = xl;
                g_Qhi[o + DK] = yh; g_Qlo[o + DK] = yl;
            } else if (z == 1) {
                size_t o = ((size_t)hd * NB + rr) * DK + hc;
                g_Khi[o] = xh; g_Klo[o] = xl;
                g_Khi[o + DK] = yh; g_Klo[o + DK] = yl;
            } else {
                size_t o = ((size_t)hd * DK + hc) * NB + rr;
                g_Vthi[o] = xh; g_Vtlo[o] = xl;
                g_Vthi[o + 1] = yh; g_Vtlo[o + 1] = yl;
            }
        }
}

// ---------------- async KV tile loads (swizzled) ----------------
__device__ __forceinline__ void load_kv_async(u32 sb, int buf, int head, int b0, int tid) {
    const u32 base = sb + SMKV(buf);
#pragma unroll
    for (int s = 0; s < 8; s++) {
        int idx = tid + s * 256;            // 0..2047
        int t   = idx >> 9;                 // 0..3
        int rem = idx & 511;
        int row = rem >> 3;
        int ch  = rem & 7;
        const __nv_bfloat16* src;
        if (t == 0)      src = g_Khi  + ((size_t)head * NB + b0 + row) * DK + ch * 8;
        else if (t == 1) src = g_Klo  + ((size_t)head * NB + b0 + row) * DK + ch * 8;
        else if (t == 2) src = g_Vthi + ((size_t)head * DK + row) * NB + b0 + ch * 8;
        else             src = g_Vtlo + ((size_t)head * DK + row) * NB + b0 + ch * 8;
        cp16(base + t * 8192 + row * 128 + ((ch ^ (row & 7)) << 4), src);
    }
}

// ---------------- fused flash attention (mma.sync, split-bf16) ----------------
__global__ __launch_bounds__(256, 1) void attn_kernel(
    const unsigned char* __restrict__ mask_u8,
    const int* __restrict__ mask_i32,
    const float* __restrict__ weight)
{
    extern __shared__ char smch[];
    const u32 sb = smem_u32(smch);
    const int tid = threadIdx.x;
    const int wid = tid >> 5, lane = tid & 31;
    const int g = lane >> 2, qd = lane & 3;
    const int head = blockIdx.y;
    const int q0 = blockIdx.x * BM;
    const int mi32 = g_mask_is_i32;

    // lane offsets for ldmatrix addressing
    const int aRow = (lane & 7) + ((lane >> 3) & 1) * 8;   // A: bit3 -> +8 rows
    const int aCol = ((lane >> 4) & 1) * 8;                // A: bit4 -> +8 cols
    const int bRow = (lane & 7) + ((lane >> 4) & 1) * 8;   // B: bit4 -> +8 rows (n)
    const int bCol = ((lane >> 3) & 1) * 8;                // B: bit3 -> +8 cols (k)

    // ---- prologue: Q (hi/lo) + KV buf0 via cp.async ----
#pragma unroll
    for (int s = 0; s < 8; s++) {
        int idx = tid + s * 256;            // 0..2047
        int t   = idx >> 10;                // 0..1 (hi/lo)
        int rem = idx & 1023;
        int row = rem >> 3;
        int ch  = rem & 7;
        const __nv_bfloat16* src = (t ? g_Qlo : g_Qhi)
            + ((size_t)head * NA + q0 + row) * DK + ch * 8;
        cp16(sb + SMQ + t * 16384 + row * 128 + ((ch ^ (row & 7)) << 4), src);
    }
    load_kv_async(sb, 0, head, 0, tid);
    cp_commit();
    cp_wait0();
    __syncthreads();

    // ---- Q fragments (persistent in registers) ----
    const int r0 = wid * 16;
    u32 qh[4][4], ql[4][4];
#pragma unroll
    for (int kt = 0; kt < 4; kt++) {
        ldsm4(swaddr(sb + SMQ, r0 + aRow, kt * 16 + aCol),
              qh[kt][0], qh[kt][1], qh[kt][2], qh[kt][3]);
        ldsm4(swaddr(sb + SMQ + 16384, r0 + aRow, kt * 16 + aCol),
              ql[kt][0], ql[kt][1], ql[kt][2], ql[kt][3]);
    }

    float oacc[8][4];
#pragma unroll
    for (int j = 0; j < 8; j++)
#pragma unroll
        for (int e = 0; e < 4; e++) oacc[j][e] = 0.0f;
    float lsumA = 0.0f, lsumB = 0.0f;

    const int rGA = q0 + r0 + g;       // global q row (low)
    const int rGB = rGA + 8;           // global q row (high)
    const float* wrA = weight + (size_t)rGA * NB + qd * 2;
    const float* wrB = weight + (size_t)rGB * NB + qd * 2;

    for (int i = 0; i < NITER; i++) {
        const int cur = i & 1;
        const int b0 = i * BN;

        if (i + 1 < NITER) {
            load_kv_async(sb, cur ^ 1, head, b0 + BN, tid);
            cp_commit();
        }

        // ---- weight + mask fragments ----
        float2 wA[8], wB[8];
        u32 mA = 0, mB = 0;
#pragma unroll
        for (int j = 0; j < 8; j++) {
            wA[j] = *(const float2*)(wrA + b0 + j * 8);
            wB[j] = *(const float2*)(wrB + b0 + j * 8);
        }
        if (mi32) {
#pragma unroll
            for (int j = 0; j < 8; j++) {
                int2 a = *(const int2*)(mask_i32 + (size_t)rGA * NB + b0 + j * 8 + qd * 2);
                int2 b = *(const int2*)(mask_i32 + (size_t)rGB * NB + b0 + j * 8 + qd * 2);
                mA |= (a.x != 0 ? 1u : 0u) << (2 * j);
                mA |= (a.y != 0 ? 1u : 0u) << (2 * j + 1);
                mB |= (b.x != 0 ? 1u : 0u) << (2 * j);
                mB |= (b.y != 0 ? 1u : 0u) << (2 * j + 1);
            }
        } else {
#pragma unroll
            for (int j = 0; j < 8; j++) {
                unsigned short a = *(const unsigned short*)(mask_u8 + (size_t)rGA * NB + b0 + j * 8 + qd * 2);
                unsigned short b = *(const unsigned short*)(mask_u8 + (size_t)rGB * NB + b0 + j * 8 + qd * 2);
                mA |= ((a & 0xff) ? 1u : 0u) << (2 * j);
                mA |= ((a >> 8)   ? 1u : 0u) << (2 * j + 1);
                mB |= ((b & 0xff) ? 1u : 0u) << (2 * j);
                mB |= ((b >> 8)   ? 1u : 0u) << (2 * j + 1);
            }
        }

        // ---- S = (Q/8) K^T via split-bf16 mma ----
        float sacc[8][4];
#pragma unroll
        for (int j = 0; j < 8; j++)
#pragma unroll
            for (int e = 0; e < 4; e++) sacc[j][e] = 0.0f;

        const u32 khB = sb + SMKV(cur), klB = khB + 8192;
#pragma unroll
        for (int kt = 0; kt < 4; kt++) {
#pragma unroll
            for (int jp = 0; jp < 4; jp++) {
                u32 k0r, k1r, k2r, k3r;
                ldsm4(swaddr(khB, jp * 16 + bRow, kt * 16 + bCol), k0r, k1r, k2r, k3r);
                mma16816(sacc[2 * jp],     qh[kt][0], qh[kt][1], qh[kt][2], qh[kt][3], k0r, k1r);
                mma16816(sacc[2 * jp + 1], qh[kt][0], qh[kt][1], qh[kt][2], qh[kt][3], k2r, k3r);
                u32 l0r, l1r, l2r, l3r;
                ldsm4(swaddr(klB, jp * 16 + bRow, kt * 16 + bCol), l0r, l1r, l2r, l3r);
                mma16816(sacc[2 * jp],     qh[kt][0], qh[kt][1], qh[kt][2], qh[kt][3], l0r, l1r);
                mma16816(sacc[2 * jp + 1], qh[kt][0], qh[kt][1], qh[kt][2], qh[kt][3], l2r, l3r);
                mma16816(sacc[2 * jp],     ql[kt][0], ql[kt][1], ql[kt][2], ql[kt][3], k0r, k1r);
                mma16816(sacc[2 * jp + 1], ql[kt][0], ql[kt][1], ql[kt][2], ql[kt][3], k2r, k3r);
            }
        }

        // ---- softmax (fixed max = 10; scores clipped to [-10,10]) ----
        u32 phi[8][2], plo[8][2];
#pragma unroll
        for (int j = 0; j < 8; j++) {
            float s0 = ((mA >> (2 * j)) & 1u)     ? sacc[j][0] + sani(wA[j].x) : -30.0f;
            float s1 = ((mA >> (2 * j + 1)) & 1u) ? sacc[j][1] + sani(wA[j].y) : -30.0f;
            float s2 = ((mB >> (2 * j)) & 1u)     ? sacc[j][2] + sani(wB[j].x) : -30.0f;
            float s3 = ((mB >> (2 * j + 1)) & 1u) ? sacc[j][3] + sani(wB[j].y) : -30.0f;
            s0 = fminf(10.0f, fmaxf(-10.0f, s0));
            s1 = fminf(10.0f, fmaxf(-10.0f, s1));
            s2 = fminf(10.0f, fmaxf(-10.0f, s2));
            s3 = fminf(10.0f, fmaxf(-10.0f, s3));
            float p0 = ex2f((s0 - 10.0f) * 1.4426950408889634f);
            float p1 = ex2f((s1 - 10.0f) * 1.4426950408889634f);
            float p2 = ex2f((s2 - 10.0f) * 1.4426950408889634f);
            float p3 = ex2f((s3 - 10.0f) * 1.4426950408889634f);
            lsumA += p0 + p1;
            lsumB += p2 + p3;
            u32 hA = packbf(p0, p1);
            u32 hB = packbf(p2, p3);
            phi[j][0] = hA;
            phi[j][1] = hB;
            plo[j][0] = packbf(p0 - bf_lo(hA), p1 - bf_hi(hA));
            plo[j][1] = packbf(p2 - bf_lo(hB), p3 - bf_hi(hB));
        }

        // ---- O += P @ V via split-bf16 mma ----
        const u32 vhB = sb + SMKV(cur) + 16384, vlB = vhB + 8192;
#pragma unroll
        for (int kt = 0; kt < 4; kt++) {
            u32 ah0 = phi[2 * kt][0], ah1 = phi[2 * kt][1];
            u32 ah2 = phi[2 * kt + 1][0], ah3 = phi[2 * kt + 1][1];
            u32 al0 = plo[2 * kt][0], al1 = plo[2 * kt][1];
            u32 al2 = plo[2 * kt + 1][0], al3 = plo[2 * kt + 1][1];
#pragma unroll
            for (int jp = 0; jp < 4; jp++) {
                u32 v0r, v1r, v2r, v3r;
                ldsm4(swaddr(vhB, jp * 16 + bRow, kt * 16 + bCol), v0r, v1r, v2r, v3r);
                mma16816(oacc[2 * jp],     ah0, ah1, ah2, ah3, v0r, v1r);
                mma16816(oacc[2 * jp + 1], ah0, ah1, ah2, ah3, v2r, v3r);
                u32 w0r, w1r, w2r, w3r;
                ldsm4(swaddr(vlB, jp * 16 + bRow, kt * 16 + bCol), w0r, w1r, w2r, w3r);
                mma16816(oacc[2 * jp],     ah0, ah1, ah2, ah3, w0r, w1r);
                mma16816(oacc[2 * jp + 1], ah0, ah1, ah2, ah3, w2r, w3r);
                mma16816(oacc[2 * jp],     al0, al1, al2, al3, v0r, v1r);
                mma16816(oacc[2 * jp + 1], al0, al1, al2, al3, v2r, v3r);
            }
        }

        if (i + 1 < NITER) cp_wait0();
        __syncthreads();
    }

    // ---- epilogue: reduce row sums over quad, normalize, store ----
    lsumA += __shfl_xor_sync(0xffffffffu, lsumA, 1);
    lsumA += __shfl_xor_sync(0xffffffffu, lsumA, 2);
    lsumB += __shfl_xor_sync(0xffffffffu, lsumB, 1);
    lsumB += __shfl_xor_sync(0xffffffffu, lsumB, 2);
    const float invA = 1.0f / lsumA;
    const float invB = 1.0f / lsumB;

    float* ctxA = g_ctx + ((size_t)head * NA + rGA) * DK + qd * 2;
    float* ctxB = g_ctx + ((size_t)head * NA + rGB) * DK + qd * 2;
#pragma unroll
    for (int j = 0; j < 8; j++) {
        *(float2*)(ctxA + j * 8) = make_float2(oacc[j][0] * invA, oacc[j][1] * invA);
        *(float2*)(ctxB + j * 8) = make_float2(oacc[j][2] * invB, oacc[j][3] * invB);
    }
}

// ---------------- finalize: head mean + influence(=1) ----------------
__global__ void finalize_kernel(float* __restrict__ out)
{
    int idx = blockIdx.x * blockDim.x + threadIdx.x;
    if (idx < NA * DK) {
        out[idx] = 0.25f * (g_ctx[idx] + g_ctx[NA * DK + idx]
                          + g_ctx[2 * NA * DK + idx] + g_ctx[3 * NA * DK + idx]);
    }
    if (idx < NA) {
        out[NA * DK + idx] = 1.0f;   // softmax rows sum to exactly 1
    }
}

// ---------------- launch ----------------
extern "C" void kernel_launch(void* const* d_in, const int* in_sizes, int n_in,
                              void* d_out, int out_size)
{
    const float* a_z    = (const float*)d_in[0];
    const float* bv_z   = (const float*)d_in[1];
    const void*  maskp  = d_in[2];
    const float* weight = (const float*)d_in[3];
    const float* Wq     = (const float*)d_in[4];
    const float* Wk     = (const float*)d_in[5];
    const float* Wv     = (const float*)d_in[6];
    float* out = (float*)d_out;

    cudaFuncSetAttribute(attn_kernel, cudaFuncAttributeMaxDynamicSharedMemorySize, SM_TOTAL);

    detect_mask_kernel<<<1, 256>>>((const unsigned*)maskp);
    proj_kernel<<<dim3(NA / 64, D / 64, 3), 256>>>(a_z, bv_z, Wq, Wk, Wv);
    attn_kernel<<<dim3(NA / BM, H), 256, SM_TOTAL>>>(
        (const unsigned char*)maskp, (const int*)maskp, weight);
    finalize_kernel<<<(NA * DK + 255) / 256, 256>>>(out);
}

// round 4
// speedup vs baseline: 1.9321x; 1.2005x over previous
#include <cuda_runtime.h>
#include <cuda_bf16.h>
#include <cuda_fp16.h>
#include <cstdint>
#include <math.h>

#define NA 4096
#define NB 4096
#define D  256
#define H  4
#define DK 64
#define BM 128
#define BN 64
#define NITER (NB / BN)   // 64

// ---------------- global scratch (no cudaMalloc allowed) ----------------
__device__ __half g_Q[H * NA * DK];        // pre-scaled by 1/8
__device__ __half g_K[H * NB * DK];
__device__ __half g_Vt[H * DK * NB];       // transposed [head][d][b]
__device__ float g_ctx[H * NA * DK];
__device__ int   g_mask_is_i32;

typedef unsigned long long u64;
typedef unsigned int u32;

// smem layout (bytes): Q 16K @0, KV buf{0,1} 16K each @16384
//   KV buf: +0 K(8K)  +8192 Vt(8K)
#define SMQ    0
#define SMKV(b) (16384 + (b) * 16384)
#define SM_TOTAL 49152

// ---------------- helpers ----------------
__device__ __forceinline__ u64 pack2(float x, float y) {
    u64 r; asm("mov.b64 %0, {%1,%2};" : "=l"(r) : "f"(x), "f"(y)); return r;
}
__device__ __forceinline__ void unpack2(u64 v, float& x, float& y) {
    asm("mov.b64 {%0,%1}, %2;" : "=f"(x), "=f"(y) : "l"(v));
}
__device__ __forceinline__ u64 fma2(u64 a, u64 b, u64 c) {
    u64 d; asm("fma.rn.f32x2 %0, %1, %2, %3;" : "=l"(d) : "l"(a), "l"(b), "l"(c)); return d;
}
__device__ __forceinline__ float sani(float x) {
    if (isnan(x)) return 0.0f;
    if (isinf(x)) return x > 0.0f ? 1.0f : -1.0f;
    return x;
}
__device__ __forceinline__ float ex2f(float x) {
    float y; asm("ex2.approx.ftz.f32 %0, %1;" : "=f"(y) : "f"(x)); return y;
}
__device__ __forceinline__ u32 smem_u32(const void* p) {
    u32 a; asm("{ .reg .u64 t; cvta.to.shared.u64 t, %1; cvt.u32.u64 %0, t; }" : "=r"(a) : "l"(p));
    return a;
}
__device__ __forceinline__ void cp16(u32 dst, const void* src) {
    asm volatile("cp.async.cg.shared.global [%0], [%1], 16;" :: "r"(dst), "l"(src));
}
__device__ __forceinline__ void cp_commit() { asm volatile("cp.async.commit_group;"); }
__device__ __forceinline__ void cp_wait0()  { asm volatile("cp.async.wait_group 0;"); }

__device__ __forceinline__ void ldsm4(u32 addr, u32& r0, u32& r1, u32& r2, u32& r3) {
    asm volatile("ldmatrix.sync.aligned.m8n8.x4.shared.b16 {%0,%1,%2,%3}, [%4];"
                 : "=r"(r0), "=r"(r1), "=r"(r2), "=r"(r3) : "r"(addr));
}
__device__ __forceinline__ void mma16816(float* c, u32 a0, u32 a1, u32 a2, u32 a3, u32 b0, u32 b1) {
    asm volatile(
        "mma.sync.aligned.m16n8k16.row.col.f32.f16.f16.f32 "
        "{%0,%1,%2,%3}, {%4,%5,%6,%7}, {%8,%9}, {%0,%1,%2,%3};"
        : "+f"(c[0]), "+f"(c[1]), "+f"(c[2]), "+f"(c[3])
        : "r"(a0), "r"(a1), "r"(a2), "r"(a3), "r"(b0), "r"(b1));
}
// pack two floats to f16x2, 'lo' in low 16 bits
__device__ __forceinline__ u32 packhf(float lo, float hi) {
    u32 d; asm("cvt.rn.f16x2.f32 %0, %1, %2;" : "=r"(d) : "f"(hi), "f"(lo)); return d;
}
// swizzled smem address: tile rows are 128B, chunk(16B) XOR row
__device__ __forceinline__ u32 swaddr(u32 base, int row, int colhalf) {
    int ch = colhalf >> 3;
    return base + row * 128 + (((ch ^ (row & 7)) << 4));
}

// ---------------- mask dtype detector ----------------
__global__ void detect_mask_kernel(const unsigned* __restrict__ m) {
    __shared__ int bad;
    if (threadIdx.x == 0) bad = 0;
    __syncthreads();
    for (int i = threadIdx.x; i < 4096; i += blockDim.x)
        if (m[i] > 1u) bad = 1;
    __syncthreads();
    if (threadIdx.x == 0) g_mask_is_i32 = bad ? 0 : 1;
}

// ---------------- projections: sanitize(X) @ W^T -> fp16 ----------------
#define PSTRIDE 68
__global__ __launch_bounds__(256) void proj_kernel(
    const float* __restrict__ a_z, const float* __restrict__ bv_z,
    const float* __restrict__ Wq, const float* __restrict__ Wk,
    const float* __restrict__ Wv)
{
    __shared__ float Xs[32][PSTRIDE];
    __shared__ float Ws[32][PSTRIDE];

    const int z = blockIdx.z;
    const float* X = (z == 0) ? a_z : bv_z;
    const float* W = (z == 0) ? Wq : (z == 1) ? Wk : Wv;
    const float outscale = (z == 0) ? 0.125f : 1.0f;

    const int tid = threadIdx.x;
    const int tx = tid & 15, ty = tid >> 4;
    const int r0 = blockIdx.x * 64, c0 = blockIdx.y * 64;

    u64 acc[2][4];
#pragma unroll
    for (int p = 0; p < 2; p++)
#pragma unroll
        for (int j = 0; j < 4; j++) acc[p][j] = 0ull;

    for (int k0 = 0; k0 < D; k0 += 32) {
        __syncthreads();
#pragma unroll
        for (int s = 0; s < 2; s++) {
            int idx = tid * 2 + s;
            int row = idx >> 3;
            int k4  = (idx & 7) * 4;
            float4 v = *(const float4*)&X[(size_t)(r0 + row) * D + k0 + k4];
            Xs[k4 + 0][row] = sani(v.x);
            Xs[k4 + 1][row] = sani(v.y);
            Xs[k4 + 2][row] = sani(v.z);
            Xs[k4 + 3][row] = sani(v.w);
            float4 w = *(const float4*)&W[(size_t)(c0 + row) * D + k0 + k4];
            Ws[k4 + 0][row] = w.x;
            Ws[k4 + 1][row] = w.y;
            Ws[k4 + 2][row] = w.z;
            Ws[k4 + 3][row] = w.w;
        }
        __syncthreads();
#pragma unroll 8
        for (int kk = 0; kk < 32; kk++) {
            const u64* ap = (const u64*)&Xs[kk][ty * 4];
            u64 a0 = ap[0], a1 = ap[1];
            float4 b = *(const float4*)&Ws[kk][tx * 4];
            u64 b0 = pack2(b.x, b.x), b1 = pack2(b.y, b.y);
            u64 b2 = pack2(b.z, b.z), b3 = pack2(b.w, b.w);
            acc[0][0] = fma2(a0, b0, acc[0][0]);
            acc[0][1] = fma2(a0, b1, acc[0][1]);
            acc[0][2] = fma2(a0, b2, acc[0][2]);
            acc[0][3] = fma2(a0, b3, acc[0][3]);
            acc[1][0] = fma2(a1, b0, acc[1][0]);
            acc[1][1] = fma2(a1, b1, acc[1][1]);
            acc[1][2] = fma2(a1, b2, acc[1][2]);
            acc[1][3] = fma2(a1, b3, acc[1][3]);
        }
    }
#pragma unroll
    for (int p = 0; p < 2; p++)
#pragma unroll
        for (int j = 0; j < 4; j++) {
            float x, y; unpack2(acc[p][j], x, y);
            x *= outscale; y *= outscale;
            const int rr = r0 + ty * 4 + p * 2;
            const int c  = c0 + tx * 4 + j;
            const int hd = c >> 6, hc = c & 63;
            __half xh = __float2half(x);
            __half yh = __float2half(y);
            if (z == 0) {
                size_t o = ((size_t)hd * NA + rr) * DK + hc;
                g_Q[o] = xh;
                g_Q[o + DK] = yh;
            } else if (z == 1) {
                size_t o = ((size_t)hd * NB + rr) * DK + hc;
                g_K[o] = xh;
                g_K[o + DK] = yh;
            } else {
                size_t o = ((size_t)hd * DK + hc) * NB + rr;
                g_Vt[o] = xh;
                g_Vt[o + 1] = yh;
            }
        }
}

// ---------------- async KV tile loads (swizzled) ----------------
__device__ __forceinline__ void load_kv_async(u32 sb, int buf, int head, int b0, int tid) {
    const u32 base = sb + SMKV(buf);
#pragma unroll
    for (int s = 0; s < 4; s++) {
        int idx = tid + s * 256;            // 0..1023
        int t   = idx >> 9;                 // 0..1 (K / Vt)
        int rem = idx & 511;
        int row = rem >> 3;
        int ch  = rem & 7;
        const __half* src = (t == 0)
            ? g_K  + ((size_t)head * NB + b0 + row) * DK + ch * 8
            : g_Vt + ((size_t)head * DK + row) * NB + b0 + ch * 8;
        cp16(base + t * 8192 + row * 128 + ((ch ^ (row & 7)) << 4), src);
    }
}

// ---------------- fused flash attention (mma.sync fp16 single-chain) ----------------
__global__ __launch_bounds__(256, 1) void attn_kernel(
    const unsigned char* __restrict__ mask_u8,
    const int* __restrict__ mask_i32,
    const float* __restrict__ weight)
{
    extern __shared__ char smch[];
    const u32 sb = smem_u32(smch);
    const int tid = threadIdx.x;
    const int wid = tid >> 5, lane = tid & 31;
    const int g = lane >> 2, qd = lane & 3;
    const int head = blockIdx.y;
    const int q0 = blockIdx.x * BM;
    const int mi32 = g_mask_is_i32;

    const int aRow = (lane & 7) + ((lane >> 3) & 1) * 8;
    const int aCol = ((lane >> 4) & 1) * 8;
    const int bRow = (lane & 7) + ((lane >> 4) & 1) * 8;
    const int bCol = ((lane >> 3) & 1) * 8;

    // ---- prologue: Q + KV buf0 via cp.async ----
#pragma unroll
    for (int s = 0; s < 4; s++) {
        int idx = tid + s * 256;            // 0..1023
        int row = idx >> 3;
        int ch  = idx & 7;
        const __half* src = g_Q + ((size_t)head * NA + q0 + row) * DK + ch * 8;
        cp16(sb + SMQ + row * 128 + ((ch ^ (row & 7)) << 4), src);
    }
    load_kv_async(sb, 0, head, 0, tid);
    cp_commit();
    cp_wait0();
    __syncthreads();

    // ---- Q fragments (persistent in registers) ----
    const int r0 = wid * 16;
    u32 qh[4][4];
#pragma unroll
    for (int kt = 0; kt < 4; kt++) {
        ldsm4(swaddr(sb + SMQ, r0 + aRow, kt * 16 + aCol),
              qh[kt][0], qh[kt][1], qh[kt][2], qh[kt][3]);
    }

    float oacc[8][4];
#pragma unroll
    for (int j = 0; j < 8; j++)
#pragma unroll
        for (int e = 0; e < 4; e++) oacc[j][e] = 0.0f;
    float lsumA = 0.0f, lsumB = 0.0f;

    const int rGA = q0 + r0 + g;       // global q row (low)
    const int rGB = rGA + 8;           // global q row (high)
    const float* wrA = weight + (size_t)rGA * NB + qd * 2;
    const float* wrB = weight + (size_t)rGB * NB + qd * 2;

    for (int i = 0; i < NITER; i++) {
        const int cur = i & 1;
        const int b0 = i * BN;

        if (i + 1 < NITER) {
            load_kv_async(sb, cur ^ 1, head, b0 + BN, tid);
            cp_commit();
        }

        // ---- weight + mask fragments ----
        float2 wA[8], wB[8];
        u32 mA = 0, mB = 0;
#pragma unroll
        for (int j = 0; j < 8; j++) {
            wA[j] = *(const float2*)(wrA + b0 + j * 8);
            wB[j] = *(const float2*)(wrB + b0 + j * 8);
        }
        if (mi32) {
#pragma unroll
            for (int j = 0; j < 8; j++) {
                int2 a = *(const int2*)(mask_i32 + (size_t)rGA * NB + b0 + j * 8 + qd * 2);
                int2 b = *(const int2*)(mask_i32 + (size_t)rGB * NB + b0 + j * 8 + qd * 2);
                mA |= (a.x != 0 ? 1u : 0u) << (2 * j);
                mA |= (a.y != 0 ? 1u : 0u) << (2 * j + 1);
                mB |= (b.x != 0 ? 1u : 0u) << (2 * j);
                mB |= (b.y != 0 ? 1u : 0u) << (2 * j + 1);
            }
        } else {
#pragma unroll
            for (int j = 0; j < 8; j++) {
                unsigned short a = *(const unsigned short*)(mask_u8 + (size_t)rGA * NB + b0 + j * 8 + qd * 2);
                unsigned short b = *(const unsigned short*)(mask_u8 + (size_t)rGB * NB + b0 + j * 8 + qd * 2);
                mA |= ((a & 0xff) ? 1u : 0u) << (2 * j);
                mA |= ((a >> 8)   ? 1u : 0u) << (2 * j + 1);
                mB |= ((b & 0xff) ? 1u : 0u) << (2 * j);
                mB |= ((b >> 8)   ? 1u : 0u) << (2 * j + 1);
            }
        }

        // ---- S = (Q/8) K^T ----
        float sacc[8][4];
#pragma unroll
        for (int j = 0; j < 8; j++)
#pragma unroll
            for (int e = 0; e < 4; e++) sacc[j][e] = 0.0f;

        const u32 kB = sb + SMKV(cur);
#pragma unroll
        for (int kt = 0; kt < 4; kt++) {
#pragma unroll
            for (int jp = 0; jp < 4; jp++) {
                u32 k0r, k1r, k2r, k3r;
                ldsm4(swaddr(kB, jp * 16 + bRow, kt * 16 + bCol), k0r, k1r, k2r, k3r);
                mma16816(sacc[2 * jp],     qh[kt][0], qh[kt][1], qh[kt][2], qh[kt][3], k0r, k1r);
                mma16816(sacc[2 * jp + 1], qh[kt][0], qh[kt][1], qh[kt][2], qh[kt][3], k2r, k3r);
            }
        }

        // ---- softmax: p' = 2^(s*log2e - 4); masked -> s = -10 (matches ref clip) ----
        u32 phf[8][2];
#pragma unroll
        for (int j = 0; j < 8; j++) {
            float s0 = ((mA >> (2 * j)) & 1u)     ? sacc[j][0] + sani(wA[j].x) : -30.0f;
            float s1 = ((mA >> (2 * j + 1)) & 1u) ? sacc[j][1] + sani(wA[j].y) : -30.0f;
            float s2 = ((mB >> (2 * j)) & 1u)     ? sacc[j][2] + sani(wB[j].x) : -30.0f;
            float s3 = ((mB >> (2 * j + 1)) & 1u) ? sacc[j][3] + sani(wB[j].y) : -30.0f;
            s0 = fminf(10.0f, fmaxf(-10.0f, s0));
            s1 = fminf(10.0f, fmaxf(-10.0f, s1));
            s2 = fminf(10.0f, fmaxf(-10.0f, s2));
            s3 = fminf(10.0f, fmaxf(-10.0f, s3));
            float p0 = ex2f(s0 * 1.4426950408889634f - 4.0f);
            float p1 = ex2f(s1 * 1.4426950408889634f - 4.0f);
            float p2 = ex2f(s2 * 1.4426950408889634f - 4.0f);
            float p3 = ex2f(s3 * 1.4426950408889634f - 4.0f);
            lsumA += p0 + p1;
            lsumB += p2 + p3;
            phf[j][0] = packhf(p0, p1);
            phf[j][1] = packhf(p2, p3);
        }

        // ---- O += P' @ V ----
        const u32 vB = sb + SMKV(cur) + 8192;
#pragma unroll
        for (int kt = 0; kt < 4; kt++) {
            u32 a0 = phf[2 * kt][0], a1 = phf[2 * kt][1];
            u32 a2 = phf[2 * kt + 1][0], a3 = phf[2 * kt + 1][1];
#pragma unroll
            for (int jp = 0; jp < 4; jp++) {
                u32 v0r, v1r, v2r, v3r;
                ldsm4(swaddr(vB, jp * 16 + bRow, kt * 16 + bCol), v0r, v1r, v2r, v3r);
                mma16816(oacc[2 * jp],     a0, a1, a2, a3, v0r, v1r);
                mma16816(oacc[2 * jp + 1], a0, a1, a2, a3, v2r, v3r);
            }
        }

        if (i + 1 < NITER) cp_wait0();
        __syncthreads();
    }

    // ---- epilogue: reduce row sums over quad, normalize, store ----
    lsumA += __shfl_xor_sync(0xffffffffu, lsumA, 1);
    lsumA += __shfl_xor_sync(0xffffffffu, lsumA, 2);
    lsumB += __shfl_xor_sync(0xffffffffu, lsumB, 1);
    lsumB += __shfl_xor_sync(0xffffffffu, lsumB, 2);
    const float invA = 1.0f / lsumA;
    const float invB = 1.0f / lsumB;

    float* ctxA = g_ctx + ((size_t)head * NA + rGA) * DK + qd * 2;
    float* ctxB = g_ctx + ((size_t)head * NA + rGB) * DK + qd * 2;
#pragma unroll
    for (int j = 0; j < 8; j++) {
        *(float2*)(ctxA + j * 8) = make_float2(oacc[j][0] * invA, oacc[j][1] * invA);
        *(float2*)(ctxB + j * 8) = make_float2(oacc[j][2] * invB, oacc[j][3] * invB);
    }
}

// ---------------- finalize: head mean + influence(=1) ----------------
__global__ void finalize_kernel(float* __restrict__ out)
{
    int idx = blockIdx.x * blockDim.x + threadIdx.x;
    if (idx < NA * DK) {
        out[idx] = 0.25f * (g_ctx[idx] + g_ctx[NA * DK + idx]
                          + g_ctx[2 * NA * DK + idx] + g_ctx[3 * NA * DK + idx]);
    }
    if (idx < NA) {
        out[NA * DK + idx] = 1.0f;   // softmax rows sum to exactly 1
    }
}

// ---------------- launch ----------------
extern "C" void kernel_launch(void* const* d_in, const int* in_sizes, int n_in,
                              void* d_out, int out_size)
{
    const float* a_z    = (const float*)d_in[0];
    const float* bv_z   = (const float*)d_in[1];
    const void*  maskp  = d_in[2];
    const float* weight = (const float*)d_in[3];
    const float* Wq     = (const float*)d_in[4];
    const float* Wk     = (const float*)d_in[5];
    const float* Wv     = (const float*)d_in[6];
    float* out = (float*)d_out;

    cudaFuncSetAttribute(attn_kernel, cudaFuncAttributeMaxDynamicSharedMemorySize, SM_TOTAL);

    detect_mask_kernel<<<1, 256>>>((const unsigned*)maskp);
    proj_kernel<<<dim3(NA / 64, D / 64, 3), 256>>>(a_z, bv_z, Wq, Wk, Wv);
    attn_kernel<<<dim3(NA / BM, H), 256, SM_TOTAL>>>(
        (const unsigned char*)maskp, (const int*)maskp, weight);
    finalize_kernel<<<(NA * DK + 255) / 256, 256>>>(out);
}

// round 5
// speedup vs baseline: 3.5827x; 1.8543x over previous
#include <cuda_runtime.h>
#include <cuda_fp16.h>
#include <cstdint>
#include <math.h>

#define NA 4096
#define NB 4096
#define D  256
#define H  4
#define DK 64
#define BM 128
#define BN 32
#define KSPLIT 2
#define KVLEN (NB / KSPLIT)        // 2048
#define NITER (KVLEN / BN)         // 64

// ---------------- global scratch (no cudaMalloc allowed) ----------------
__device__ __half g_Q[H * NA * DK];        // pre-scaled by 1/8
__device__ __half g_K[H * NB * DK];
__device__ __half g_Vt[H * DK * NB];       // transposed [head][d][b]
__device__ float g_pO[KSPLIT * H * NA * DK];   // partial O
__device__ float g_pl[KSPLIT * H * NA];        // partial row sums
__device__ unsigned g_mbits[NA * (NB / 32)];   // bit-packed mask
__device__ int   g_mask_is_i32;

typedef unsigned long long u64;
typedef unsigned int u32;

// smem layout (bytes): Q 16K @0, KV buf{0,1} 12K each @16384
//   KV buf: +0 K(4K: 32 rows x 128B)  +4096 Vt(8K: 64 rows x 128B, 64B data + pad)
#define SMQ    0
#define SMKV(b) (16384 + (b) * 12288)
#define SM_TOTAL 40960

// ---------------- helpers ----------------
__device__ __forceinline__ u64 pack2(float x, float y) {
    u64 r; asm("mov.b64 %0, {%1,%2};" : "=l"(r) : "f"(x), "f"(y)); return r;
}
__device__ __forceinline__ void unpack2(u64 v, float& x, float& y) {
    asm("mov.b64 {%0,%1}, %2;" : "=f"(x), "=f"(y) : "l"(v));
}
__device__ __forceinline__ u64 fma2(u64 a, u64 b, u64 c) {
    u64 d; asm("fma.rn.f32x2 %0, %1, %2, %3;" : "=l"(d) : "l"(a), "l"(b), "l"(c)); return d;
}
__device__ __forceinline__ float sani(float x) {
    if (isnan(x)) return 0.0f;
    if (isinf(x)) return x > 0.0f ? 1.0f : -1.0f;
    return x;
}
__device__ __forceinline__ float ex2f(float x) {
    float y; asm("ex2.approx.ftz.f32 %0, %1;" : "=f"(y) : "f"(x)); return y;
}
__device__ __forceinline__ u32 smem_u32(const void* p) {
    u32 a; asm("{ .reg .u64 t; cvta.to.shared.u64 t, %1; cvt.u32.u64 %0, t; }" : "=r"(a) : "l"(p));
    return a;
}
__device__ __forceinline__ void cp16(u32 dst, const void* src) {
    asm volatile("cp.async.cg.shared.global [%0], [%1], 16;" :: "r"(dst), "l"(src));
}
__device__ __forceinline__ void cp_commit() { asm volatile("cp.async.commit_group;"); }
__device__ __forceinline__ void cp_wait0()  { asm volatile("cp.async.wait_group 0;"); }

__device__ __forceinline__ void ldsm4(u32 addr, u32& r0, u32& r1, u32& r2, u32& r3) {
    asm volatile("ldmatrix.sync.aligned.m8n8.x4.shared.b16 {%0,%1,%2,%3}, [%4];"
                 : "=r"(r0), "=r"(r1), "=r"(r2), "=r"(r3) : "r"(addr));
}
__device__ __forceinline__ void mma16816(float* c, u32 a0, u32 a1, u32 a2, u32 a3, u32 b0, u32 b1) {
    asm volatile(
        "mma.sync.aligned.m16n8k16.row.col.f32.f16.f16.f32 "
        "{%0,%1,%2,%3}, {%4,%5,%6,%7}, {%8,%9}, {%0,%1,%2,%3};"
        : "+f"(c[0]), "+f"(c[1]), "+f"(c[2]), "+f"(c[3])
        : "r"(a0), "r"(a1), "r"(a2), "r"(a3), "r"(b0), "r"(b1));
}
__device__ __forceinline__ u32 packhf(float lo, float hi) {
    u32 d; asm("cvt.rn.f16x2.f32 %0, %1, %2;" : "=r"(d) : "f"(hi), "f"(lo)); return d;
}
__device__ __forceinline__ u32 swaddr(u32 base, int row, int colhalf) {
    int ch = colhalf >> 3;
    return base + row * 128 + (((ch ^ (row & 7)) << 4));
}

// ---------------- mask dtype detector ----------------
__global__ void detect_mask_kernel(const unsigned* __restrict__ m) {
    __shared__ int bad;
    if (threadIdx.x == 0) bad = 0;
    __syncthreads();
    for (int i = threadIdx.x; i < 4096; i += blockDim.x)
        if (m[i] > 1u) bad = 1;
    __syncthreads();
    if (threadIdx.x == 0) g_mask_is_i32 = bad ? 0 : 1;
}

// ---------------- mask bit-pack: 1 word = 32 cols of one row ----------------
__global__ __launch_bounds__(256) void pack_mask_kernel(
    const unsigned char* __restrict__ m8, const int* __restrict__ m32)
{
    const int w = blockIdx.x * 256 + threadIdx.x;   // 0 .. 524287
    const int row = w >> 7, wc = w & 127;
    u32 bits = 0;
    if (g_mask_is_i32) {
        const int4* p = (const int4*)(m32 + (size_t)row * NB + wc * 32);
#pragma unroll
        for (int t = 0; t < 8; t++) {
            int4 v = p[t];
            bits |= (v.x != 0 ? 1u : 0u) << (4 * t + 0);
            bits |= (v.y != 0 ? 1u : 0u) << (4 * t + 1);
            bits |= (v.z != 0 ? 1u : 0u) << (4 * t + 2);
            bits |= (v.w != 0 ? 1u : 0u) << (4 * t + 3);
        }
    } else {
        const uint4* p = (const uint4*)(m8 + (size_t)row * NB + wc * 32);
#pragma unroll
        for (int t = 0; t < 2; t++) {
            uint4 v = p[t];
            u32 wd[4] = {v.x, v.y, v.z, v.w};
#pragma unroll
            for (int q = 0; q < 4; q++)
#pragma unroll
                for (int b = 0; b < 4; b++)
                    bits |= (((wd[q] >> (8 * b)) & 0xffu) ? 1u : 0u) << (t * 16 + q * 4 + b);
        }
    }
    g_mbits[w] = bits;
}

// ---------------- projections: sanitize(X) @ W^T -> fp16 ----------------
#define PSTRIDE 68
__global__ __launch_bounds__(256) void proj_kernel(
    const float* __restrict__ a_z, const float* __restrict__ bv_z,
    const float* __restrict__ Wq, const float* __restrict__ Wk,
    const float* __restrict__ Wv)
{
    __shared__ float Xs[32][PSTRIDE];
    __shared__ float Ws[32][PSTRIDE];

    const int z = blockIdx.z;
    const float* X = (z == 0) ? a_z : bv_z;
    const float* W = (z == 0) ? Wq : (z == 1) ? Wk : Wv;
    const float outscale = (z == 0) ? 0.125f : 1.0f;

    const int tid = threadIdx.x;
    const int tx = tid & 15, ty = tid >> 4;
    const int r0 = blockIdx.x * 64, c0 = blockIdx.y * 64;

    u64 acc[2][4];
#pragma unroll
    for (int p = 0; p < 2; p++)
#pragma unroll
        for (int j = 0; j < 4; j++) acc[p][j] = 0ull;

    for (int k0 = 0; k0 < D; k0 += 32) {
        __syncthreads();
#pragma unroll
        for (int s = 0; s < 2; s++) {
            int idx = tid * 2 + s;
            int row = idx >> 3;
            int k4  = (idx & 7) * 4;
            float4 v = *(const float4*)&X[(size_t)(r0 + row) * D + k0 + k4];
            Xs[k4 + 0][row] = sani(v.x);
            Xs[k4 + 1][row] = sani(v.y);
            Xs[k4 + 2][row] = sani(v.z);
            Xs[k4 + 3][row] = sani(v.w);
            float4 w = *(const float4*)&W[(size_t)(c0 + row) * D + k0 + k4];
            Ws[k4 + 0][row] = w.x;
            Ws[k4 + 1][row] = w.y;
            Ws[k4 + 2][row] = w.z;
            Ws[k4 + 3][row] = w.w;
        }
        __syncthreads();
#pragma unroll 8
        for (int kk = 0; kk < 32; kk++) {
            const u64* ap = (const u64*)&Xs[kk][ty * 4];
            u64 a0 = ap[0], a1 = ap[1];
            float4 b = *(const float4*)&Ws[kk][tx * 4];
            u64 b0 = pack2(b.x, b.x), b1 = pack2(b.y, b.y);
            u64 b2 = pack2(b.z, b.z), b3 = pack2(b.w, b.w);
            acc[0][0] = fma2(a0, b0, acc[0][0]);
            acc[0][1] = fma2(a0, b1, acc[0][1]);
            acc[0][2] = fma2(a0, b2, acc[0][2]);
            acc[0][3] = fma2(a0, b3, acc[0][3]);
            acc[1][0] = fma2(a1, b0, acc[1][0]);
            acc[1][1] = fma2(a1, b1, acc[1][1]);
            acc[1][2] = fma2(a1, b2, acc[1][2]);
            acc[1][3] = fma2(a1, b3, acc[1][3]);
        }
    }
#pragma unroll
    for (int p = 0; p < 2; p++)
#pragma unroll
        for (int j = 0; j < 4; j++) {
            float x, y; unpack2(acc[p][j], x, y);
            x *= outscale; y *= outscale;
            const int rr = r0 + ty * 4 + p * 2;
            const int c  = c0 + tx * 4 + j;
            const int hd = c >> 6, hc = c & 63;
            __half xh = __float2half(x);
            __half yh = __float2half(y);
            if (z == 0) {
                size_t o = ((size_t)hd * NA + rr) * DK + hc;
                g_Q[o] = xh;
                g_Q[o + DK] = yh;
            } else if (z == 1) {
                size_t o = ((size_t)hd * NB + rr) * DK + hc;
                g_K[o] = xh;
                g_K[o + DK] = yh;
            } else {
                size_t o = ((size_t)hd * DK + hc) * NB + rr;
                g_Vt[o] = xh;
                g_Vt[o + 1] = yh;
            }
        }
}

// ---------------- async KV tile loads (swizzled; 512 chunks / 256 thr) ----------------
__device__ __forceinline__ void load_kv_async(u32 sb, int buf, int head, int b0, int tid) {
    const u32 base = sb + SMKV(buf);
    {   // K: 32 rows x 8 chunks
        int row = tid >> 3, ch = tid & 7;
        const __half* src = g_K + ((size_t)head * NB + b0 + row) * DK + ch * 8;
        cp16(base + row * 128 + ((ch ^ (row & 7)) << 4), src);
    }
    {   // Vt: 64 rows x 4 chunks (rows padded to 128B)
        int row = tid >> 2, ch = tid & 3;
        const __half* src = g_Vt + ((size_t)head * DK + row) * NB + b0 + ch * 8;
        cp16(base + 4096 + row * 128 + ((ch ^ (row & 7)) << 4), src);
    }
}

// ---------------- fused flash attention (fp16 mma.sync, split-KV) ----------------
__global__ __launch_bounds__(256, 2) void attn_kernel(const float* __restrict__ weight)
{
    extern __shared__ char smch[];
    const u32 sb = smem_u32(smch);
    const int tid = threadIdx.x;
    const int wid = tid >> 5, lane = tid & 31;
    const int g = lane >> 2, qd = lane & 3;
    const int head = blockIdx.x;
    const int q0 = blockIdx.y * BM;
    const int split = blockIdx.z;
    const int bbase = split * KVLEN;

    const int aRow = (lane & 7) + ((lane >> 3) & 1) * 8;
    const int aCol = ((lane >> 4) & 1) * 8;
    const int bRow = (lane & 7) + ((lane >> 4) & 1) * 8;
    const int bCol = ((lane >> 3) & 1) * 8;

    // ---- prologue: Q + KV buf0 ----
#pragma unroll
    for (int s = 0; s < 4; s++) {
        int idx = tid + s * 256;
        int row = idx >> 3;
        int ch  = idx & 7;
        const __half* src = g_Q + ((size_t)head * NA + q0 + row) * DK + ch * 8;
        cp16(sb + SMQ + row * 128 + ((ch ^ (row & 7)) << 4), src);
    }
    load_kv_async(sb, 0, head, bbase, tid);
    cp_commit();
    cp_wait0();
    __syncthreads();

    const int r0 = wid * 16;
    u32 qh[4][4];
#pragma unroll
    for (int kt = 0; kt < 4; kt++) {
        ldsm4(swaddr(sb + SMQ, r0 + aRow, kt * 16 + aCol),
              qh[kt][0], qh[kt][1], qh[kt][2], qh[kt][3]);
    }

    float oacc[8][4];
#pragma unroll
    for (int j = 0; j < 8; j++)
#pragma unroll
        for (int e = 0; e < 4; e++) oacc[j][e] = 0.0f;
    float lsumA = 0.0f, lsumB = 0.0f;

    const int rGA = q0 + r0 + g;
    const int rGB = rGA + 8;
    const float* wrA = weight + (size_t)rGA * NB + qd * 2;
    const float* wrB = weight + (size_t)rGB * NB + qd * 2;
    const unsigned* mwA = g_mbits + rGA * (NB / 32) + bbase / 32;
    const unsigned* mwB = g_mbits + rGB * (NB / 32) + bbase / 32;

    for (int i = 0; i < NITER; i++) {
        const int cur = i & 1;
        const int b0 = bbase + i * BN;

        if (i + 1 < NITER) {
            load_kv_async(sb, cur ^ 1, head, b0 + BN, tid);
            cp_commit();
        }

        // ---- weight + packed mask ----
        float2 wA[4], wB[4];
#pragma unroll
        for (int j = 0; j < 4; j++) {
            wA[j] = *(const float2*)(wrA + b0 + j * 8);
            wB[j] = *(const float2*)(wrB + b0 + j * 8);
        }
        const u32 mA = mwA[i];
        const u32 mB = mwB[i];

        // ---- S = (Q/8) K^T ----
        float sacc[4][4];
#pragma unroll
        for (int j = 0; j < 4; j++)
#pragma unroll
            for (int e = 0; e < 4; e++) sacc[j][e] = 0.0f;

        const u32 kB = sb + SMKV(cur);
#pragma unroll
        for (int kt = 0; kt < 4; kt++) {
#pragma unroll
            for (int jp = 0; jp < 2; jp++) {
                u32 k0r, k1r, k2r, k3r;
                ldsm4(swaddr(kB, jp * 16 + bRow, kt * 16 + bCol), k0r, k1r, k2r, k3r);
                mma16816(sacc[2 * jp],     qh[kt][0], qh[kt][1], qh[kt][2], qh[kt][3], k0r, k1r);
                mma16816(sacc[2 * jp + 1], qh[kt][0], qh[kt][1], qh[kt][2], qh[kt][3], k2r, k3r);
            }
        }

        // ---- softmax: p' = 2^(s*log2e - 4); masked -> s=-30 (p'~0) ----
        u32 phf[4][2];
#pragma unroll
        for (int j = 0; j < 4; j++) {
            const int bA = qd * 2 + j * 8;
            float s0 = ((mA >> bA) & 1u)       ? sacc[j][0] + wA[j].x : -30.0f;
            float s1 = ((mA >> (bA + 1)) & 1u) ? sacc[j][1] + wA[j].y : -30.0f;
            float s2 = ((mB >> bA) & 1u)       ? sacc[j][2] + wB[j].x : -30.0f;
            float s3 = ((mB >> (bA + 1)) & 1u) ? sacc[j][3] + wB[j].y : -30.0f;
            s0 = fminf(10.0f, fmaxf(-10.0f, s0));
            s1 = fminf(10.0f, fmaxf(-10.0f, s1));
            s2 = fminf(10.0f, fmaxf(-10.0f, s2));
            s3 = fminf(10.0f, fmaxf(-10.0f, s3));
            float p0 = ex2f(s0 * 1.4426950408889634f - 4.0f);
            float p1 = ex2f(s1 * 1.4426950408889634f - 4.0f);
            float p2 = ex2f(s2 * 1.4426950408889634f - 4.0f);
            float p3 = ex2f(s3 * 1.4426950408889634f - 4.0f);
            lsumA += p0 + p1;
            lsumB += p2 + p3;
            phf[j][0] = packhf(p0, p1);
            phf[j][1] = packhf(p2, p3);
        }

        // ---- O += P' @ V ----
        const u32 vB = sb + SMKV(cur) + 4096;
#pragma unroll
        for (int kt = 0; kt < 2; kt++) {
            u32 a0 = phf[2 * kt][0], a1 = phf[2 * kt][1];
            u32 a2 = phf[2 * kt + 1][0], a3 = phf[2 * kt + 1][1];
#pragma unroll
            for (int jp = 0; jp < 4; jp++) {
                u32 v0r, v1r, v2r, v3r;
                ldsm4(swaddr(vB, jp * 16 + bRow, kt * 16 + bCol), v0r, v1r, v2r, v3r);
                mma16816(oacc[2 * jp],     a0, a1, a2, a3, v0r, v1r);
                mma16816(oacc[2 * jp + 1], a0, a1, a2, a3, v2r, v3r);
            }
        }

        if (i + 1 < NITER) cp_wait0();
        __syncthreads();
    }

    // ---- epilogue: partial O + partial l (additive across splits) ----
    lsumA += __shfl_xor_sync(0xffffffffu, lsumA, 1);
    lsumA += __shfl_xor_sync(0xffffffffu, lsumA, 2);
    lsumB += __shfl_xor_sync(0xffffffffu, lsumB, 1);
    lsumB += __shfl_xor_sync(0xffffffffu, lsumB, 2);

    const size_t po = ((size_t)(split * H + head) * NA);
    if (qd == 0) {
        g_pl[po + rGA] = lsumA;
        g_pl[po + rGB] = lsumB;
    }
    float* pA = g_pO + (po + rGA) * DK + qd * 2;
    float* pB = g_pO + (po + rGB) * DK + qd * 2;
#pragma unroll
    for (int j = 0; j < 8; j++) {
        *(float2*)(pA + j * 8) = make_float2(oacc[j][0], oacc[j][1]);
        *(float2*)(pB + j * 8) = make_float2(oacc[j][2], oacc[j][3]);
    }
}

// ---------------- finalize: combine splits, head mean, influence ----------------
__global__ void finalize_kernel(float* __restrict__ out)
{
    int idx = blockIdx.x * blockDim.x + threadIdx.x;
    if (idx < NA * DK) {
        const int row = idx >> 6, col = idx & 63;
        float acc = 0.0f;
#pragma unroll
        for (int h = 0; h < H; h++) {
            float o = g_pO[((size_t)h * NA + row) * DK + col]
                    + g_pO[((size_t)(H + h) * NA + row) * DK + col];
            float l = g_pl[(size_t)h * NA + row] + g_pl[(size_t)(H + h) * NA + row];
            acc += o / l;
        }
        out[idx] = 0.25f * acc;
    }
    if (idx < NA) {
        out[NA * DK + idx] = 1.0f;   // softmax rows sum to exactly 1
    }
}

// ---------------- launch ----------------
extern "C" void kernel_launch(void* const* d_in, const int* in_sizes, int n_in,
                              void* d_out, int out_size)
{
    const float* a_z    = (const float*)d_in[0];
    const float* bv_z   = (const float*)d_in[1];
    const void*  maskp  = d_in[2];
    const float* weight = (const float*)d_in[3];
    const float* Wq     = (const float*)d_in[4];
    const float* Wk     = (const float*)d_in[5];
    const float* Wv     = (const float*)d_in[6];
    float* out = (float*)d_out;

    cudaFuncSetAttribute(attn_kernel, cudaFuncAttributeMaxDynamicSharedMemorySize, SM_TOTAL);

    detect_mask_kernel<<<1, 256>>>((const unsigned*)maskp);
    pack_mask_kernel<<<(NA * (NB / 32)) / 256, 256>>>(
        (const unsigned char*)maskp, (const int*)maskp);
    proj_kernel<<<dim3(NA / 64, D / 64, 3), 256>>>(a_z, bv_z, Wq, Wk, Wv);
    attn_kernel<<<dim3(H, NA / BM, KSPLIT), 256, SM_TOTAL>>>(weight);
    finalize_kernel<<<(NA * DK + 255) / 256, 256>>>(out);
}

// round 6
// speedup vs baseline: 3.8669x; 1.0793x over previous
#include <cuda_runtime.h>
#include <cuda_fp16.h>
#include <cstdint>
#include <math.h>

#define NA 4096
#define NB 4096
#define D  256
#define H  4
#define DK 64
#define BM 128
#define BN 32
#define KSPLIT 2
#define KVLEN (NB / KSPLIT)        // 2048
#define NITER (KVLEN / BN)         // 64

// ---------------- global scratch (no cudaMalloc allowed) ----------------
__device__ __half g_Q[H * NA * DK];        // pre-scaled by 1/8
__device__ __half g_K[H * NB * DK];
__device__ __half g_Vt[H * DK * NB];       // transposed [head][d][b]
__device__ float g_pO[KSPLIT * H * NA * DK];   // partial O
__device__ float g_pl[KSPLIT * H * NA];        // partial row sums
__device__ unsigned g_mbits[NA * (NB / 32)];   // bit-packed mask
__device__ int   g_mask_is_i32;

typedef unsigned long long u64;
typedef unsigned int u32;

// smem layout (bytes): Q 16K @0, KV buf{0,1} 12K each @16384
#define SMQ    0
#define SMKV(b) (16384 + (b) * 12288)
#define SM_TOTAL 40960

// ---------------- helpers ----------------
__device__ __forceinline__ u64 pack2(float x, float y) {
    u64 r; asm("mov.b64 %0, {%1,%2};" : "=l"(r) : "f"(x), "f"(y)); return r;
}
__device__ __forceinline__ void unpack2(u64 v, float& x, float& y) {
    asm("mov.b64 {%0,%1}, %2;" : "=f"(x), "=f"(y) : "l"(v));
}
__device__ __forceinline__ u64 fma2(u64 a, u64 b, u64 c) {
    u64 d; asm("fma.rn.f32x2 %0, %1, %2, %3;" : "=l"(d) : "l"(a), "l"(b), "l"(c)); return d;
}
__device__ __forceinline__ float sani(float x) {
    if (isnan(x)) return 0.0f;
    if (isinf(x)) return x > 0.0f ? 1.0f : -1.0f;
    return x;
}
__device__ __forceinline__ float ex2f(float x) {
    float y; asm("ex2.approx.ftz.f32 %0, %1;" : "=f"(y) : "f"(x)); return y;
}
__device__ __forceinline__ u32 smem_u32(const void* p) {
    u32 a; asm("{ .reg .u64 t; cvta.to.shared.u64 t, %1; cvt.u32.u64 %0, t; }" : "=r"(a) : "l"(p));
    return a;
}
__device__ __forceinline__ void cp16(u32 dst, const void* src) {
    asm volatile("cp.async.cg.shared.global [%0], [%1], 16;" :: "r"(dst), "l"(src));
}
__device__ __forceinline__ void cp_commit() { asm volatile("cp.async.commit_group;"); }
__device__ __forceinline__ void cp_wait0()  { asm volatile("cp.async.wait_group 0;"); }

__device__ __forceinline__ void ldsm4(u32 addr, u32& r0, u32& r1, u32& r2, u32& r3) {
    asm volatile("ldmatrix.sync.aligned.m8n8.x4.shared.b16 {%0,%1,%2,%3}, [%4];"
                 : "=r"(r0), "=r"(r1), "=r"(r2), "=r"(r3) : "r"(addr));
}
__device__ __forceinline__ void mma16816(float* c, u32 a0, u32 a1, u32 a2, u32 a3, u32 b0, u32 b1) {
    asm volatile(
        "mma.sync.aligned.m16n8k16.row.col.f32.f16.f16.f32 "
        "{%0,%1,%2,%3}, {%4,%5,%6,%7}, {%8,%9}, {%0,%1,%2,%3};"
        : "+f"(c[0]), "+f"(c[1]), "+f"(c[2]), "+f"(c[3])
        : "r"(a0), "r"(a1), "r"(a2), "r"(a3), "r"(b0), "r"(b1));
}
__device__ __forceinline__ u32 packhf(float lo, float hi) {
    u32 d; asm("cvt.rn.f16x2.f32 %0, %1, %2;" : "=r"(d) : "f"(hi), "f"(lo)); return d;
}
__device__ __forceinline__ u32 swaddr(u32 base, int row, int colhalf) {
    int ch = colhalf >> 3;
    return base + row * 128 + (((ch ^ (row & 7)) << 4));
}

// ---------------- mask dtype detector ----------------
__global__ void detect_mask_kernel(const unsigned* __restrict__ m) {
    __shared__ int bad;
    if (threadIdx.x == 0) bad = 0;
    __syncthreads();
    for (int i = threadIdx.x; i < 4096; i += blockDim.x)
        if (m[i] > 1u) bad = 1;
    __syncthreads();
    if (threadIdx.x == 0) g_mask_is_i32 = bad ? 0 : 1;
}

// ---------------- merged projections + mask pack ----------------
// grid (64, 32, 4): z<3 -> proj (y<4 only), z==3 -> mask bit-pack
#define PSTRIDE 68
__global__ __launch_bounds__(256) void projpack_kernel(
    const float* __restrict__ a_z, const float* __restrict__ bv_z,
    const float* __restrict__ Wq, const float* __restrict__ Wk,
    const float* __restrict__ Wv,
    const unsigned char* __restrict__ m8, const int* __restrict__ m32)
{
    const int z = blockIdx.z;
    const int tid = threadIdx.x;

    if (z == 3) {
        // ---- mask bit-pack: one u32 word = 32 cols of one row ----
        const int w = (blockIdx.x * 32 + blockIdx.y) * 256 + tid;  // 0..524287
        const int row = w >> 7, wc = w & 127;
        u32 bits = 0;
        if (g_mask_is_i32) {
            const int4* p = (const int4*)(m32 + (size_t)row * NB + wc * 32);
#pragma unroll
            for (int t = 0; t < 8; t++) {
                int4 v = p[t];
                bits |= (v.x != 0 ? 1u : 0u) << (4 * t + 0);
                bits |= (v.y != 0 ? 1u : 0u) << (4 * t + 1);
                bits |= (v.z != 0 ? 1u : 0u) << (4 * t + 2);
                bits |= (v.w != 0 ? 1u : 0u) << (4 * t + 3);
            }
        } else {
            const uint4* p = (const uint4*)(m8 + (size_t)row * NB + wc * 32);
#pragma unroll
            for (int t = 0; t < 2; t++) {
                uint4 v = p[t];
                u32 wd[4] = {v.x, v.y, v.z, v.w};
#pragma unroll
                for (int q = 0; q < 4; q++)
#pragma unroll
                    for (int b = 0; b < 4; b++)
                        bits |= (((wd[q] >> (8 * b)) & 0xffu) ? 1u : 0u) << (t * 16 + q * 4 + b);
            }
        }
        g_mbits[w] = bits;
        return;
    }

    if (blockIdx.y >= 4) return;

    __shared__ float Xs[32][PSTRIDE];
    __shared__ float Ws[32][PSTRIDE];

    const float* X = (z == 0) ? a_z : bv_z;
    const float* W = (z == 0) ? Wq : (z == 1) ? Wk : Wv;
    const float outscale = (z == 0) ? 0.125f : 1.0f;

    const int tx = tid & 15, ty = tid >> 4;
    const int r0 = blockIdx.x * 64, c0 = blockIdx.y * 64;

    u64 acc[2][4];
#pragma unroll
    for (int p = 0; p < 2; p++)
#pragma unroll
        for (int j = 0; j < 4; j++) acc[p][j] = 0ull;

    for (int k0 = 0; k0 < D; k0 += 32) {
        __syncthreads();
#pragma unroll
        for (int s = 0; s < 2; s++) {
            int idx = tid * 2 + s;
            int row = idx >> 3;
            int k4  = (idx & 7) * 4;
            float4 v = *(const float4*)&X[(size_t)(r0 + row) * D + k0 + k4];
            Xs[k4 + 0][row] = sani(v.x);
            Xs[k4 + 1][row] = sani(v.y);
            Xs[k4 + 2][row] = sani(v.z);
            Xs[k4 + 3][row] = sani(v.w);
            float4 w = *(const float4*)&W[(size_t)(c0 + row) * D + k0 + k4];
            Ws[k4 + 0][row] = w.x;
            Ws[k4 + 1][row] = w.y;
            Ws[k4 + 2][row] = w.z;
            Ws[k4 + 3][row] = w.w;
        }
        __syncthreads();
#pragma unroll 8
        for (int kk = 0; kk < 32; kk++) {
            const u64* ap = (const u64*)&Xs[kk][ty * 4];
            u64 a0 = ap[0], a1 = ap[1];
            float4 b = *(const float4*)&Ws[kk][tx * 4];
            u64 b0 = pack2(b.x, b.x), b1 = pack2(b.y, b.y);
            u64 b2 = pack2(b.z, b.z), b3 = pack2(b.w, b.w);
            acc[0][0] = fma2(a0, b0, acc[0][0]);
            acc[0][1] = fma2(a0, b1, acc[0][1]);
            acc[0][2] = fma2(a0, b2, acc[0][2]);
            acc[0][3] = fma2(a0, b3, acc[0][3]);
            acc[1][0] = fma2(a1, b0, acc[1][0]);
            acc[1][1] = fma2(a1, b1, acc[1][1]);
            acc[1][2] = fma2(a1, b2, acc[1][2]);
            acc[1][3] = fma2(a1, b3, acc[1][3]);
        }
    }
#pragma unroll
    for (int p = 0; p < 2; p++)
#pragma unroll
        for (int j = 0; j < 4; j++) {
            float x, y; unpack2(acc[p][j], x, y);
            x *= outscale; y *= outscale;
            const int rr = r0 + ty * 4 + p * 2;
            const int c  = c0 + tx * 4 + j;
            const int hd = c >> 6, hc = c & 63;
            __half xh = __float2half(x);
            __half yh = __float2half(y);
            if (z == 0) {
                size_t o = ((size_t)hd * NA + rr) * DK + hc;
                g_Q[o] = xh;
                g_Q[o + DK] = yh;
            } else if (z == 1) {
                size_t o = ((size_t)hd * NB + rr) * DK + hc;
                g_K[o] = xh;
                g_K[o + DK] = yh;
            } else {
                size_t o = ((size_t)hd * DK + hc) * NB + rr;
                g_Vt[o] = xh;
                g_Vt[o + 1] = yh;
            }
        }
}

// ---------------- async KV tile loads (swizzled; 512 chunks / 128 thr) ----------------
__device__ __forceinline__ void load_kv_async(u32 sb, int buf, int head, int b0, int tid) {
    const u32 base = sb + SMKV(buf);
#pragma unroll
    for (int s = 0; s < 2; s++) {   // K: 32 rows x 8 chunks
        int idx = tid + s * 128;
        int row = idx >> 3, ch = idx & 7;
        const __half* src = g_K + ((size_t)head * NB + b0 + row) * DK + ch * 8;
        cp16(base + row * 128 + ((ch ^ (row & 7)) << 4), src);
    }
#pragma unroll
    for (int s = 0; s < 2; s++) {   // Vt: 64 rows x 4 chunks
        int idx = tid + s * 128;
        int row = idx >> 2, ch = idx & 3;
        const __half* src = g_Vt + ((size_t)head * DK + row) * NB + b0 + ch * 8;
        cp16(base + 4096 + row * 128 + ((ch ^ (row & 7)) << 4), src);
    }
}

// ---------------- fused flash attention: 4 warps, M=32/warp ----------------
__global__ __launch_bounds__(128, 2) void attn_kernel(const float* __restrict__ weight)
{
    extern __shared__ char smch[];
    const u32 sb = smem_u32(smch);
    const int tid = threadIdx.x;
    const int w = tid >> 5, lane = tid & 31;
    const int g = lane >> 2, qd = lane & 3;
    const int head = blockIdx.x;
    const int q0 = blockIdx.y * BM;
    const int split = blockIdx.z;
    const int bbase = split * KVLEN;

    const int aRow = (lane & 7) + ((lane >> 3) & 1) * 8;
    const int aCol = ((lane >> 4) & 1) * 8;
    const int bRow = (lane & 7) + ((lane >> 4) & 1) * 8;
    const int bCol = ((lane >> 3) & 1) * 8;

    // ---- prologue: Q + KV buf0 ----
#pragma unroll
    for (int s = 0; s < 8; s++) {
        int idx = tid + s * 128;
        int row = idx >> 3;
        int ch  = idx & 7;
        const __half* src = g_Q + ((size_t)head * NA + q0 + row) * DK + ch * 8;
        cp16(sb + SMQ + row * 128 + ((ch ^ (row & 7)) << 4), src);
    }
    load_kv_async(sb, 0, head, bbase, tid);
    cp_commit();
    cp_wait0();
    __syncthreads();

    // ---- Q fragments: 2 row-tiles x 4 k-tiles ----
    const int r0 = w * 32;
    u32 qh[2][4][4];
#pragma unroll
    for (int rt = 0; rt < 2; rt++)
#pragma unroll
        for (int kt = 0; kt < 4; kt++)
            ldsm4(swaddr(sb + SMQ, r0 + rt * 16 + aRow, kt * 16 + aCol),
                  qh[rt][kt][0], qh[rt][kt][1], qh[rt][kt][2], qh[rt][kt][3]);

    float oacc[2][8][4];
#pragma unroll
    for (int rt = 0; rt < 2; rt++)
#pragma unroll
        for (int j = 0; j < 8; j++)
#pragma unroll
            for (int e = 0; e < 4; e++) oacc[rt][j][e] = 0.0f;
    float lsum[2][2] = {{0.f, 0.f}, {0.f, 0.f}};   // [rt][A/B]

    // 4 rows per thread: rt*16 + {0,8} offsets from base row
    const int rbase = q0 + r0 + g;
    const float* wbase = weight + (size_t)rbase * NB + qd * 2;
    const unsigned* mbase = g_mbits + (size_t)rbase * (NB / 32) + bbase / 32;

    for (int i = 0; i < NITER; i++) {
        const int cur = i & 1;
        const int b0 = bbase + i * BN;

        if (i + 1 < NITER) {
            load_kv_async(sb, cur ^ 1, head, b0 + BN, tid);
            cp_commit();
        }

        // ---- weight + packed mask for 4 rows ----
        float2 wr[2][2][4];   // [rt][A/B][ntile]
        u32 mr[2][2];
#pragma unroll
        for (int rt = 0; rt < 2; rt++) {
            mr[rt][0] = mbase[(rt * 16 + 0) * (NB / 32) + i];
            mr[rt][1] = mbase[(rt * 16 + 8) * (NB / 32) + i];
#pragma unroll
            for (int j = 0; j < 4; j++) {
                wr[rt][0][j] = *(const float2*)(wbase + (size_t)(rt * 16 + 0) * NB + b0 + j * 8);
                wr[rt][1][j] = *(const float2*)(wbase + (size_t)(rt * 16 + 8) * NB + b0 + j * 8);
            }
        }

        // ---- S = (Q/8) K^T : shared K frags across both row-tiles ----
        float sacc[2][4][4];
#pragma unroll
        for (int rt = 0; rt < 2; rt++)
#pragma unroll
            for (int j = 0; j < 4; j++)
#pragma unroll
                for (int e = 0; e < 4; e++) sacc[rt][j][e] = 0.0f;

        const u32 kB = sb + SMKV(cur);
#pragma unroll
        for (int kt = 0; kt < 4; kt++) {
#pragma unroll
            for (int jp = 0; jp < 2; jp++) {
                u32 k0r, k1r, k2r, k3r;
                ldsm4(swaddr(kB, jp * 16 + bRow, kt * 16 + bCol), k0r, k1r, k2r, k3r);
#pragma unroll
                for (int rt = 0; rt < 2; rt++) {
                    mma16816(sacc[rt][2 * jp],     qh[rt][kt][0], qh[rt][kt][1], qh[rt][kt][2], qh[rt][kt][3], k0r, k1r);
                    mma16816(sacc[rt][2 * jp + 1], qh[rt][kt][0], qh[rt][kt][1], qh[rt][kt][2], qh[rt][kt][3], k2r, k3r);
                }
            }
        }

        // ---- softmax: p' = 2^(s*log2e - 4) ----
        u32 phf[2][4][2];
#pragma unroll
        for (int rt = 0; rt < 2; rt++) {
#pragma unroll
            for (int j = 0; j < 4; j++) {
                const int bA = qd * 2 + j * 8;
                float s0 = ((mr[rt][0] >> bA) & 1u)       ? sacc[rt][j][0] + wr[rt][0][j].x : -30.0f;
                float s1 = ((mr[rt][0] >> (bA + 1)) & 1u) ? sacc[rt][j][1] + wr[rt][0][j].y : -30.0f;
                float s2 = ((mr[rt][1] >> bA) & 1u)       ? sacc[rt][j][2] + wr[rt][1][j].x : -30.0f;
                float s3 = ((mr[rt][1] >> (bA + 1)) & 1u) ? sacc[rt][j][3] + wr[rt][1][j].y : -30.0f;
                s0 = fminf(10.0f, fmaxf(-10.0f, s0));
                s1 = fminf(10.0f, fmaxf(-10.0f, s1));
                s2 = fminf(10.0f, fmaxf(-10.0f, s2));
                s3 = fminf(10.0f, fmaxf(-10.0f, s3));
                float p0 = ex2f(s0 * 1.4426950408889634f - 4.0f);
                float p1 = ex2f(s1 * 1.4426950408889634f - 4.0f);
                float p2 = ex2f(s2 * 1.4426950408889634f - 4.0f);
                float p3 = ex2f(s3 * 1.4426950408889634f - 4.0f);
                lsum[rt][0] += p0 + p1;
                lsum[rt][1] += p2 + p3;
                phf[rt][j][0] = packhf(p0, p1);
                phf[rt][j][1] = packhf(p2, p3);
            }
        }

        // ---- O += P' @ V : shared V frags across both row-tiles ----
        const u32 vB = sb + SMKV(cur) + 4096;
#pragma unroll
        for (int kt = 0; kt < 2; kt++) {
#pragma unroll
            for (int jp = 0; jp < 4; jp++) {
                u32 v0r, v1r, v2r, v3r;
                ldsm4(swaddr(vB, jp * 16 + bRow, kt * 16 + bCol), v0r, v1r, v2r, v3r);
#pragma unroll
                for (int rt = 0; rt < 2; rt++) {
                    u32 a0 = phf[rt][2 * kt][0], a1 = phf[rt][2 * kt][1];
                    u32 a2 = phf[rt][2 * kt + 1][0], a3 = phf[rt][2 * kt + 1][1];
                    mma16816(oacc[rt][2 * jp],     a0, a1, a2, a3, v0r, v1r);
                    mma16816(oacc[rt][2 * jp + 1], a0, a1, a2, a3, v2r, v3r);
                }
            }
        }

        if (i + 1 < NITER) cp_wait0();
        __syncthreads();
    }

    // ---- epilogue: partial O + partial l (additive across splits) ----
    const size_t po = ((size_t)(split * H + head) * NA);
#pragma unroll
    for (int rt = 0; rt < 2; rt++) {
        float lA = lsum[rt][0], lB = lsum[rt][1];
        lA += __shfl_xor_sync(0xffffffffu, lA, 1);
        lA += __shfl_xor_sync(0xffffffffu, lA, 2);
        lB += __shfl_xor_sync(0xffffffffu, lB, 1);
        lB += __shfl_xor_sync(0xffffffffu, lB, 2);
        const int rGA = rbase + rt * 16;
        const int rGB = rGA + 8;
        if (qd == 0) {
            g_pl[po + rGA] = lA;
            g_pl[po + rGB] = lB;
        }
        float* pA = g_pO + (po + rGA) * DK + qd * 2;
        float* pB = g_pO + (po + rGB) * DK + qd * 2;
#pragma unroll
        for (int j = 0; j < 8; j++) {
            *(float2*)(pA + j * 8) = make_float2(oacc[rt][j][0], oacc[rt][j][1]);
            *(float2*)(pB + j * 8) = make_float2(oacc[rt][j][2], oacc[rt][j][3]);
        }
    }
}

// ---------------- finalize: combine splits, head mean, influence ----------------
__global__ void finalize_kernel(float* __restrict__ out)
{
    int idx = blockIdx.x * blockDim.x + threadIdx.x;
    if (idx < NA * DK) {
        const int row = idx >> 6, col = idx & 63;
        float acc = 0.0f;
#pragma unroll
        for (int h = 0; h < H; h++) {
            float o = g_pO[((size_t)h * NA + row) * DK + col]
                    + g_pO[((size_t)(H + h) * NA + row) * DK + col];
            float l = g_pl[(size_t)h * NA + row] + g_pl[(size_t)(H + h) * NA + row];
            acc += o / l;
        }
        out[idx] = 0.25f * acc;
    }
    if (idx < NA) {
        out[NA * DK + idx] = 1.0f;   // softmax rows sum to exactly 1
    }
}

// ---------------- launch ----------------
extern "C" void kernel_launch(void* const* d_in, const int* in_sizes, int n_in,
                              void* d_out, int out_size)
{
    const float* a_z    = (const float*)d_in[0];
    const float* bv_z   = (const float*)d_in[1];
    const void*  maskp  = d_in[2];
    const float* weight = (const float*)d_in[3];
    const float* Wq     = (const float*)d_in[4];
    const float* Wk     = (const float*)d_in[5];
    const float* Wv     = (const float*)d_in[6];
    float* out = (float*)d_out;

    cudaFuncSetAttribute(attn_kernel, cudaFuncAttributeMaxDynamicSharedMemorySize, SM_TOTAL);

    detect_mask_kernel<<<1, 256>>>((const unsigned*)maskp);
    projpack_kernel<<<dim3(64, 32, 4), 256>>>(a_z, bv_z, Wq, Wk, Wv,
        (const unsigned char*)maskp, (const int*)maskp);
    attn_kernel<<<dim3(H, NA / BM, KSPLIT), 128, SM_TOTAL>>>(weight);
    finalize_kernel<<<(NA * DK + 255) / 256, 256>>>(out);
}

// round 7
// speedup vs baseline: 4.1912x; 1.0839x over previous
#include <cuda_runtime.h>
#include <cuda_fp16.h>
#include <cstdint>
#include <math.h>

#define NA 4096
#define NB 4096
#define D  256
#define H  4
#define DK 64
#define BM 128
#define BN 32
#define KSPLIT 3
#define ITER_S0 43                 // splits get 43/43/42 iters (128 total)

// ---------------- global scratch (no cudaMalloc allowed) ----------------
__device__ __half g_Q[H * NA * DK];        // pre-scaled by 1/8
__device__ __half g_K[H * NB * DK];
__device__ __half g_Vt[H * DK * NB];       // transposed [head][d][b]
__device__ float g_pO[KSPLIT * H * NA * DK];   // partial O
__device__ float g_pl[KSPLIT * H * NA];        // partial row sums
__device__ unsigned g_mbits[NA * (NB / 32)];   // bit-packed mask
__device__ int   g_mask_is_i32;

typedef unsigned long long u64;
typedef unsigned int u32;

// smem layout (bytes):
//   Q      @0      16384
//   KV[b]  @16384 + b*12288   (K 4096 @+0, Vt 8192 @+4096)
//   W[b]   @40960 + b*16384   (128 rows x 128B, swizzled)
#define SMQ    0
#define SMKV(b) (16384 + (b) * 12288)
#define SMW(b)  (40960 + (b) * 16384)
#define SM_TOTAL 73728

// ---------------- helpers ----------------
__device__ __forceinline__ u64 pack2(float x, float y) {
    u64 r; asm("mov.b64 %0, {%1,%2};" : "=l"(r) : "f"(x), "f"(y)); return r;
}
__device__ __forceinline__ void unpack2(u64 v, float& x, float& y) {
    asm("mov.b64 {%0,%1}, %2;" : "=f"(x), "=f"(y) : "l"(v));
}
__device__ __forceinline__ u64 fma2(u64 a, u64 b, u64 c) {
    u64 d; asm("fma.rn.f32x2 %0, %1, %2, %3;" : "=l"(d) : "l"(a), "l"(b), "l"(c)); return d;
}
__device__ __forceinline__ float sani(float x) {
    if (isnan(x)) return 0.0f;
    if (isinf(x)) return x > 0.0f ? 1.0f : -1.0f;
    return x;
}
__device__ __forceinline__ float ex2f(float x) {
    float y; asm("ex2.approx.ftz.f32 %0, %1;" : "=f"(y) : "f"(x)); return y;
}
__device__ __forceinline__ u32 smem_u32(const void* p) {
    u32 a; asm("{ .reg .u64 t; cvta.to.shared.u64 t, %1; cvt.u32.u64 %0, t; }" : "=r"(a) : "l"(p));
    return a;
}
__device__ __forceinline__ void cp16(u32 dst, const void* src) {
    asm volatile("cp.async.cg.shared.global [%0], [%1], 16;" :: "r"(dst), "l"(src));
}
__device__ __forceinline__ void cp_commit() { asm volatile("cp.async.commit_group;"); }
__device__ __forceinline__ void cp_wait0()  { asm volatile("cp.async.wait_group 0;"); }

__device__ __forceinline__ void ldsm4(u32 addr, u32& r0, u32& r1, u32& r2, u32& r3) {
    asm volatile("ldmatrix.sync.aligned.m8n8.x4.shared.b16 {%0,%1,%2,%3}, [%4];"
                 : "=r"(r0), "=r"(r1), "=r"(r2), "=r"(r3) : "r"(addr));
}
__device__ __forceinline__ void mma16816(float* c, u32 a0, u32 a1, u32 a2, u32 a3, u32 b0, u32 b1) {
    asm volatile(
        "mma.sync.aligned.m16n8k16.row.col.f32.f16.f16.f32 "
        "{%0,%1,%2,%3}, {%4,%5,%6,%7}, {%8,%9}, {%0,%1,%2,%3};"
        : "+f"(c[0]), "+f"(c[1]), "+f"(c[2]), "+f"(c[3])
        : "r"(a0), "r"(a1), "r"(a2), "r"(a3), "r"(b0), "r"(b1));
}
__device__ __forceinline__ u32 packhf(float lo, float hi) {
    u32 d; asm("cvt.rn.f16x2.f32 %0, %1, %2;" : "=r"(d) : "f"(hi), "f"(lo)); return d;
}
__device__ __forceinline__ u32 swaddr(u32 base, int row, int colhalf) {
    int ch = colhalf >> 3;
    return base + row * 128 + (((ch ^ (row & 7)) << 4));
}

// ---------------- mask dtype detector ----------------
__global__ void detect_mask_kernel(const unsigned* __restrict__ m) {
    __shared__ int bad;
    if (threadIdx.x == 0) bad = 0;
    __syncthreads();
    for (int i = threadIdx.x; i < 4096; i += blockDim.x)
        if (m[i] > 1u) bad = 1;
    __syncthreads();
    if (threadIdx.x == 0) g_mask_is_i32 = bad ? 0 : 1;
}

// ---------------- merged projections + mask pack ----------------
#define PSTRIDE 68
__global__ __launch_bounds__(256) void projpack_kernel(
    const float* __restrict__ a_z, const float* __restrict__ bv_z,
    const float* __restrict__ Wq, const float* __restrict__ Wk,
    const float* __restrict__ Wv,
    const unsigned char* __restrict__ m8, const int* __restrict__ m32)
{
    const int z = blockIdx.z;
    const int tid = threadIdx.x;

    if (z == 3) {
        const int w = (blockIdx.x * 32 + blockIdx.y) * 256 + tid;
        const int row = w >> 7, wc = w & 127;
        u32 bits = 0;
        if (g_mask_is_i32) {
            const int4* p = (const int4*)(m32 + (size_t)row * NB + wc * 32);
#pragma unroll
            for (int t = 0; t < 8; t++) {
                int4 v = p[t];
                bits |= (v.x != 0 ? 1u : 0u) << (4 * t + 0);
                bits |= (v.y != 0 ? 1u : 0u) << (4 * t + 1);
                bits |= (v.z != 0 ? 1u : 0u) << (4 * t + 2);
                bits |= (v.w != 0 ? 1u : 0u) << (4 * t + 3);
            }
        } else {
            const uint4* p = (const uint4*)(m8 + (size_t)row * NB + wc * 32);
#pragma unroll
            for (int t = 0; t < 2; t++) {
                uint4 v = p[t];
                u32 wd[4] = {v.x, v.y, v.z, v.w};
#pragma unroll
                for (int q = 0; q < 4; q++)
#pragma unroll
                    for (int b = 0; b < 4; b++)
                        bits |= (((wd[q] >> (8 * b)) & 0xffu) ? 1u : 0u) << (t * 16 + q * 4 + b);
            }
        }
        g_mbits[w] = bits;
        return;
    }

    if (blockIdx.y >= 4) return;

    __shared__ float Xs[32][PSTRIDE];
    __shared__ float Ws[32][PSTRIDE];

    const float* X = (z == 0) ? a_z : bv_z;
    const float* W = (z == 0) ? Wq : (z == 1) ? Wk : Wv;
    const float outscale = (z == 0) ? 0.125f : 1.0f;

    const int tx = tid & 15, ty = tid >> 4;
    const int r0 = blockIdx.x * 64, c0 = blockIdx.y * 64;

    u64 acc[2][4];
#pragma unroll
    for (int p = 0; p < 2; p++)
#pragma unroll
        for (int j = 0; j < 4; j++) acc[p][j] = 0ull;

    for (int k0 = 0; k0 < D; k0 += 32) {
        __syncthreads();
#pragma unroll
        for (int s = 0; s < 2; s++) {
            int idx = tid * 2 + s;
            int row = idx >> 3;
            int k4  = (idx & 7) * 4;
            float4 v = *(const float4*)&X[(size_t)(r0 + row) * D + k0 + k4];
            Xs[k4 + 0][row] = sani(v.x);
            Xs[k4 + 1][row] = sani(v.y);
            Xs[k4 + 2][row] = sani(v.z);
            Xs[k4 + 3][row] = sani(v.w);
            float4 w = *(const float4*)&W[(size_t)(c0 + row) * D + k0 + k4];
            Ws[k4 + 0][row] = w.x;
            Ws[k4 + 1][row] = w.y;
            Ws[k4 + 2][row] = w.z;
            Ws[k4 + 3][row] = w.w;
        }
        __syncthreads();
#pragma unroll 8
        for (int kk = 0; kk < 32; kk++) {
            const u64* ap = (const u64*)&Xs[kk][ty * 4];
            u64 a0 = ap[0], a1 = ap[1];
            float4 b = *(const float4*)&Ws[kk][tx * 4];
            u64 b0 = pack2(b.x, b.x), b1 = pack2(b.y, b.y);
            u64 b2 = pack2(b.z, b.z), b3 = pack2(b.w, b.w);
            acc[0][0] = fma2(a0, b0, acc[0][0]);
            acc[0][1] = fma2(a0, b1, acc[0][1]);
            acc[0][2] = fma2(a0, b2, acc[0][2]);
            acc[0][3] = fma2(a0, b3, acc[0][3]);
            acc[1][0] = fma2(a1, b0, acc[1][0]);
            acc[1][1] = fma2(a1, b1, acc[1][1]);
            acc[1][2] = fma2(a1, b2, acc[1][2]);
            acc[1][3] = fma2(a1, b3, acc[1][3]);
        }
    }
#pragma unroll
    for (int p = 0; p < 2; p++)
#pragma unroll
        for (int j = 0; j < 4; j++) {
            float x, y; unpack2(acc[p][j], x, y);
            x *= outscale; y *= outscale;
            const int rr = r0 + ty * 4 + p * 2;
            const int c  = c0 + tx * 4 + j;
            const int hd = c >> 6, hc = c & 63;
            __half xh = __float2half(x);
            __half yh = __float2half(y);
            if (z == 0) {
                size_t o = ((size_t)hd * NA + rr) * DK + hc;
                g_Q[o] = xh;
                g_Q[o + DK] = yh;
            } else if (z == 1) {
                size_t o = ((size_t)hd * NB + rr) * DK + hc;
                g_K[o] = xh;
                g_K[o + DK] = yh;
            } else {
                size_t o = ((size_t)hd * DK + hc) * NB + rr;
                g_Vt[o] = xh;
                g_Vt[o + 1] = yh;
            }
        }
}

// ---------------- async tile loads (swizzled) ----------------
__device__ __forceinline__ void load_kvw_async(u32 sb, int buf, int head, int b0,
                                               const float* __restrict__ weight,
                                               int q0, int tid) {
    const u32 base = sb + SMKV(buf);
#pragma unroll
    for (int s = 0; s < 2; s++) {   // K: 32 rows x 8 chunks
        int idx = tid + s * 128;
        int row = idx >> 3, ch = idx & 7;
        const __half* src = g_K + ((size_t)head * NB + b0 + row) * DK + ch * 8;
        cp16(base + row * 128 + ((ch ^ (row & 7)) << 4), src);
    }
#pragma unroll
    for (int s = 0; s < 2; s++) {   // Vt: 64 rows x 4 chunks
        int idx = tid + s * 128;
        int row = idx >> 2, ch = idx & 3;
        const __half* src = g_Vt + ((size_t)head * DK + row) * NB + b0 + ch * 8;
        cp16(base + 4096 + row * 128 + ((ch ^ (row & 7)) << 4), src);
    }
    const u32 wbase = sb + SMW(buf);
#pragma unroll
    for (int s = 0; s < 8; s++) {   // W: 128 rows x 8 chunks (32 floats/row)
        int idx = tid + s * 128;
        int row = idx >> 3, ch = idx & 7;
        const float* src = weight + (size_t)(q0 + row) * NB + b0 + ch * 4;
        cp16(wbase + row * 128 + ((ch ^ (row & 7)) << 4), src);
    }
}

// ---------------- fused flash attention: 4 warps, M=32/warp, W in smem ----------------
__global__ __launch_bounds__(128, 3) void attn_kernel(const float* __restrict__ weight)
{
    extern __shared__ char smch[];
    const u32 sb = smem_u32(smch);
    const int tid = threadIdx.x;
    const int w = tid >> 5, lane = tid & 31;
    const int g = lane >> 2, qd = lane & 3;
    const int head = blockIdx.x;
    const int q0 = blockIdx.y * BM;
    const int split = blockIdx.z;
    const int istart = split * ITER_S0;
    const int niter = (split == 2) ? 42 : ITER_S0;

    const int aRow = (lane & 7) + ((lane >> 3) & 1) * 8;
    const int aCol = ((lane >> 4) & 1) * 8;
    const int bRow = (lane & 7) + ((lane >> 4) & 1) * 8;
    const int bCol = ((lane >> 3) & 1) * 8;

    // ---- prologue: Q + KV/W buf0 ----
#pragma unroll
    for (int s = 0; s < 8; s++) {
        int idx = tid + s * 128;
        int row = idx >> 3;
        int ch  = idx & 7;
        const __half* src = g_Q + ((size_t)head * NA + q0 + row) * DK + ch * 8;
        cp16(sb + SMQ + row * 128 + ((ch ^ (row & 7)) << 4), src);
    }
    load_kvw_async(sb, 0, head, istart * BN, weight, q0, tid);
    cp_commit();
    cp_wait0();
    __syncthreads();

    // ---- Q fragments: 2 row-tiles x 4 k-tiles ----
    const int r0 = w * 32;
    u32 qh[2][4][4];
#pragma unroll
    for (int rt = 0; rt < 2; rt++)
#pragma unroll
        for (int kt = 0; kt < 4; kt++)
            ldsm4(swaddr(sb + SMQ, r0 + rt * 16 + aRow, kt * 16 + aCol),
                  qh[rt][kt][0], qh[rt][kt][1], qh[rt][kt][2], qh[rt][kt][3]);

    float oacc[2][8][4];
#pragma unroll
    for (int rt = 0; rt < 2; rt++)
#pragma unroll
        for (int j = 0; j < 8; j++)
#pragma unroll
            for (int e = 0; e < 4; e++) oacc[rt][j][e] = 0.0f;
    float lsum[2][2] = {{0.f, 0.f}, {0.f, 0.f}};

    const int rbase = q0 + r0 + g;
    const unsigned* mbase = g_mbits + (size_t)rbase * (NB / 32) + istart;
    // W smem read base offsets for this thread's 4 rows (local rows r0+g + {0,8,16,24})
    const int wrow0 = r0 + g;

    for (int i = 0; i < niter; i++) {
        const int cur = i & 1;

        if (i + 1 < niter) {
            load_kvw_async(sb, cur ^ 1, head, (istart + i + 1) * BN, weight, q0, tid);
            cp_commit();
        }

        // ---- packed mask for 4 rows ----
        u32 mr[2][2];
#pragma unroll
        for (int rt = 0; rt < 2; rt++) {
            mr[rt][0] = mbase[(rt * 16 + 0) * (NB / 32) + i];
            mr[rt][1] = mbase[(rt * 16 + 8) * (NB / 32) + i];
        }

        // ---- S = (Q/8) K^T : shared K frags across both row-tiles ----
        float sacc[2][4][4];
#pragma unroll
        for (int rt = 0; rt < 2; rt++)
#pragma unroll
            for (int j = 0; j < 4; j++)
#pragma unroll
                for (int e = 0; e < 4; e++) sacc[rt][j][e] = 0.0f;

        const u32 kB = sb + SMKV(cur);
#pragma unroll
        for (int kt = 0; kt < 4; kt++) {
#pragma unroll
            for (int jp = 0; jp < 2; jp++) {
                u32 k0r, k1r, k2r, k3r;
                ldsm4(swaddr(kB, jp * 16 + bRow, kt * 16 + bCol), k0r, k1r, k2r, k3r);
#pragma unroll
                for (int rt = 0; rt < 2; rt++) {
                    mma16816(sacc[rt][2 * jp],     qh[rt][kt][0], qh[rt][kt][1], qh[rt][kt][2], qh[rt][kt][3], k0r, k1r);
                    mma16816(sacc[rt][2 * jp + 1], qh[rt][kt][0], qh[rt][kt][1], qh[rt][kt][2], qh[rt][kt][3], k2r, k3r);
                }
            }
        }

        // ---- softmax: p' = 2^(s*log2e - 4); weight read from smem ----
        const u32 wB = sb + SMW(cur);
        u32 phf[2][4][2];
#pragma unroll
        for (int rt = 0; rt < 2; rt++) {
#pragma unroll
            for (int j = 0; j < 4; j++) {
                const int bA = qd * 2 + j * 8;
                const int chk = 2 * j + (qd >> 1);
                const int boff = (qd & 1) * 8;
                // rows: wrow0 + rt*16 + {0,8}
                const int rA = wrow0 + rt * 16;
                const int rB = rA + 8;
                float2 wvA = *(const float2*)(smch + (wB - sb) + rA * 128 + ((chk ^ (rA & 7)) << 4) + boff);
                float2 wvB = *(const float2*)(smch + (wB - sb) + rB * 128 + ((chk ^ (rB & 7)) << 4) + boff);
                float s0 = ((mr[rt][0] >> bA) & 1u)       ? sacc[rt][j][0] + wvA.x : -30.0f;
                float s1 = ((mr[rt][0] >> (bA + 1)) & 1u) ? sacc[rt][j][1] + wvA.y : -30.0f;
                float s2 = ((mr[rt][1] >> bA) & 1u)       ? sacc[rt][j][2] + wvB.x : -30.0f;
                float s3 = ((mr[rt][1] >> (bA + 1)) & 1u) ? sacc[rt][j][3] + wvB.y : -30.0f;
                s0 = fminf(10.0f, fmaxf(-10.0f, s0));
                s1 = fminf(10.0f, fmaxf(-10.0f, s1));
                s2 = fminf(10.0f, fmaxf(-10.0f, s2));
                s3 = fminf(10.0f, fmaxf(-10.0f, s3));
                float p0 = ex2f(s0 * 1.4426950408889634f - 4.0f);
                float p1 = ex2f(s1 * 1.4426950408889634f - 4.0f);
                float p2 = ex2f(s2 * 1.4426950408889634f - 4.0f);
                float p3 = ex2f(s3 * 1.4426950408889634f - 4.0f);
                lsum[rt][0] += p0 + p1;
                lsum[rt][1] += p2 + p3;
                phf[rt][j][0] = packhf(p0, p1);
                phf[rt][j][1] = packhf(p2, p3);
            }
        }

        // ---- O += P' @ V : shared V frags across both row-tiles ----
        const u32 vB = sb + SMKV(cur) + 4096;
#pragma unroll
        for (int kt = 0; kt < 2; kt++) {
#pragma unroll
            for (int jp = 0; jp < 4; jp++) {
                u32 v0r, v1r, v2r, v3r;
                ldsm4(swaddr(vB, jp * 16 + bRow, kt * 16 + bCol), v0r, v1r, v2r, v3r);
#pragma unroll
                for (int rt = 0; rt < 2; rt++) {
                    u32 a0 = phf[rt][2 * kt][0], a1 = phf[rt][2 * kt][1];
                    u32 a2 = phf[rt][2 * kt + 1][0], a3 = phf[rt][2 * kt + 1][1];
                    mma16816(oacc[rt][2 * jp],     a0, a1, a2, a3, v0r, v1r);
                    mma16816(oacc[rt][2 * jp + 1], a0, a1, a2, a3, v2r, v3r);
                }
            }
        }

        if (i + 1 < niter) cp_wait0();
        __syncthreads();
    }

    // ---- epilogue: partial O + partial l (additive across splits) ----
    const size_t po = ((size_t)(split * H + head) * NA);
#pragma unroll
    for (int rt = 0; rt < 2; rt++) {
        float lA = lsum[rt][0], lB = lsum[rt][1];
        lA += __shfl_xor_sync(0xffffffffu, lA, 1);
        lA += __shfl_xor_sync(0xffffffffu, lA, 2);
        lB += __shfl_xor_sync(0xffffffffu, lB, 1);
        lB += __shfl_xor_sync(0xffffffffu, lB, 2);
        const int rGA = rbase + rt * 16;
        const int rGB = rGA + 8;
        if (qd == 0) {
            g_pl[po + rGA] = lA;
            g_pl[po + rGB] = lB;
        }
        float* pA = g_pO + (po + rGA) * DK + qd * 2;
        float* pB = g_pO + (po + rGB) * DK + qd * 2;
#pragma unroll
        for (int j = 0; j < 8; j++) {
            *(float2*)(pA + j * 8) = make_float2(oacc[rt][j][0], oacc[rt][j][1]);
            *(float2*)(pB + j * 8) = make_float2(oacc[rt][j][2], oacc[rt][j][3]);
        }
    }
}

// ---------------- finalize: combine splits, head mean, influence ----------------
__global__ void finalize_kernel(float* __restrict__ out)
{
    int idx = blockIdx.x * blockDim.x + threadIdx.x;
    if (idx < NA * DK) {
        const int row = idx >> 6, col = idx & 63;
        float acc = 0.0f;
#pragma unroll
        for (int h = 0; h < H; h++) {
            float o = 0.0f, l = 0.0f;
#pragma unroll
            for (int s = 0; s < KSPLIT; s++) {
                o += g_pO[((size_t)(s * H + h) * NA + row) * DK + col];
                l += g_pl[(size_t)(s * H + h) * NA + row];
            }
            acc += o / l;
        }
        out[idx] = 0.25f * acc;
    }
    if (idx < NA) {
        out[NA * DK + idx] = 1.0f;   // softmax rows sum to exactly 1
    }
}

// ---------------- launch ----------------
extern "C" void kernel_launch(void* const* d_in, const int* in_sizes, int n_in,
                              void* d_out, int out_size)
{
    const float* a_z    = (const float*)d_in[0];
    const float* bv_z   = (const float*)d_in[1];
    const void*  maskp  = d_in[2];
    const float* weight = (const float*)d_in[3];
    const float* Wq     = (const float*)d_in[4];
    const float* Wk     = (const float*)d_in[5];
    const float* Wv     = (const float*)d_in[6];
    float* out = (float*)d_out;

    cudaFuncSetAttribute(attn_kernel, cudaFuncAttributeMaxDynamicSharedMemorySize, SM_TOTAL);

    detect_mask_kernel<<<1, 256>>>((const unsigned*)maskp);
    projpack_kernel<<<dim3(64, 32, 4), 256>>>(a_z, bv_z, Wq, Wk, Wv,
        (const unsigned char*)maskp, (const int*)maskp);
    attn_kernel<<<dim3(H, NA / BM, KSPLIT), 128, SM_TOTAL>>>(weight);
    finalize_kernel<<<(NA * DK + 255) / 256, 256>>>(out);
}